// round 1
// baseline (speedup 1.0000x reference)
#include <cuda_runtime.h>
#include <cstdint>
#include <cstddef>

// ---------------------------------------------------------------------------
// TSABlock: x@Wd^T+bd  (+ temb)  -> qkv -> per-row 8x8 head-softmax -> @Wo^T+bo
// Key fact: HEADS==CLIP==8 makes the torch-.view attention fully row-local.
// ---------------------------------------------------------------------------

#define BSZ     8192
#define CLIP_N  8
#define IN_CH   1024
#define OUT_CH  512
#define T_DIM   512
#define ROWS    (BSZ * CLIP_N)   // 65536

// Scratch (device-global: no allocations allowed in kernel_launch)
__device__ float g_temb[(size_t)BSZ * OUT_CH];
__device__ float g_x2  [(size_t)ROWS * OUT_CH];
__device__ float g_qkv [(size_t)ROWS * 3 * OUT_CH];
__device__ float g_attn[(size_t)ROWS * OUT_CH];

// ---------------- packed f32x2 helpers (Blackwell FFMA2 path) --------------
__device__ __forceinline__ unsigned long long pack2(float x) {
    unsigned long long r;
    unsigned u = __float_as_uint(x);
    asm("mov.b64 %0, {%1, %1};" : "=l"(r) : "r"(u));
    return r;
}
__device__ __forceinline__ void fma2(unsigned long long& d,
                                     unsigned long long a,
                                     unsigned long long b) {
    asm("fma.rn.f32x2 %0, %1, %2, %0;" : "+l"(d) : "l"(a), "l"(b));
}
__device__ __forceinline__ float2 unpack2(unsigned long long v) {
    unsigned lo, hi;
    asm("mov.b64 {%0, %1}, %2;" : "=r"(lo), "=r"(hi) : "l"(v));
    float2 f;
    f.x = __uint_as_float(lo);
    f.y = __uint_as_float(hi);
    return f;
}

// ---------------------------------------------------------------------------
// GEMM: C[M,N] = A[M,K] @ W[N,K]^T + bias[N]  (+ extra[m>>3, N] if MODE==1)
// Both A and W are K-contiguous (TN dot-product GEMM).
// Block tile 128x128, BK=8, 256 threads, 8x8 per thread as 8x4 f32x2 accums.
// M % 128 == 0, N % 128 == 0, K % 8 == 0 for all call sites.
// ---------------------------------------------------------------------------
template <int MODE>
__global__ __launch_bounds__(256, 2)
void gemm_kernel(const float* __restrict__ A,
                 const float* __restrict__ W,
                 const float* __restrict__ bias,
                 const float* __restrict__ extra,
                 float* __restrict__ C,
                 int M, int N, int K)
{
    __shared__ __align__(16) float As[8][128];
    __shared__ __align__(16) float Ws[8][128];

    const int tid   = threadIdx.x;
    const int tx    = tid & 15;        // 0..15 -> n
    const int ty    = tid >> 4;        // 0..15 -> m
    const int mB    = blockIdx.y * 128;
    const int nB    = blockIdx.x * 128;
    const int lrow  = tid >> 1;        // 0..127 (tile row being loaded)
    const int kpart = (tid & 1) * 4;   // 0 or 4

    const float* gA = A + (size_t)(mB + lrow) * K + kpart;
    const float* gW = W + (size_t)(nB + lrow) * K + kpart;

    unsigned long long acc[8][4];
#pragma unroll
    for (int i = 0; i < 8; i++)
#pragma unroll
        for (int p = 0; p < 4; p++) acc[i][p] = 0ull;

    float4 ra = *(const float4*)gA;
    float4 rw = *(const float4*)gW;

    const int nK = K >> 3;
    for (int ks = 0; ks < nK; ks++) {
        As[kpart + 0][lrow] = ra.x; As[kpart + 1][lrow] = ra.y;
        As[kpart + 2][lrow] = ra.z; As[kpart + 3][lrow] = ra.w;
        Ws[kpart + 0][lrow] = rw.x; Ws[kpart + 1][lrow] = rw.y;
        Ws[kpart + 2][lrow] = rw.z; Ws[kpart + 3][lrow] = rw.w;
        __syncthreads();

        if (ks + 1 < nK) {
            ra = *(const float4*)(gA + (size_t)(ks + 1) * 8);
            rw = *(const float4*)(gW + (size_t)(ks + 1) * 8);
        }

#pragma unroll
        for (int kk = 0; kk < 8; kk++) {
            float4 a0 = *(const float4*)&As[kk][ty * 8];
            float4 a1 = *(const float4*)&As[kk][ty * 8 + 4];
            ulonglong2 b0 = *(const ulonglong2*)&Ws[kk][tx * 8];
            ulonglong2 b1 = *(const ulonglong2*)&Ws[kk][tx * 8 + 4];
            float av[8] = {a0.x, a0.y, a0.z, a0.w, a1.x, a1.y, a1.z, a1.w};
#pragma unroll
            for (int i = 0; i < 8; i++) {
                unsigned long long ap = pack2(av[i]);
                fma2(acc[i][0], ap, b0.x);
                fma2(acc[i][1], ap, b0.y);
                fma2(acc[i][2], ap, b1.x);
                fma2(acc[i][3], ap, b1.y);
            }
        }
        __syncthreads();
    }

    // Epilogue
    const int nBase = nB + tx * 8;
    float bv[8];
#pragma unroll
    for (int q = 0; q < 8; q++) bv[q] = bias[nBase + q];

#pragma unroll
    for (int i = 0; i < 8; i++) {
        const int m = mB + ty * 8 + i;
        float* crow = C + (size_t)m * N + nBase;
        const float* ex = nullptr;
        if (MODE) ex = extra + (size_t)(m >> 3) * N + nBase;
#pragma unroll
        for (int p = 0; p < 4; p++) {
            float2 v = unpack2(acc[i][p]);
            v.x += bv[2 * p];
            v.y += bv[2 * p + 1];
            if (MODE) {
                v.x += ex[2 * p];
                v.y += ex[2 * p + 1];
            }
            *(float2*)(crow + 2 * p) = v;
        }
    }
}

// ---------------------------------------------------------------------------
// Per-row attention: for each row r (one token), qkv[r] = [q(512)|k(512)|v(512)].
// Heads attend to each other within the row (the .view quirk):
//   w[qh,kh] = softmax_kh( (q_h . k_h) / 8 ),  attn[qh*64+c] = sum_kh w*v[kh*64+c]
// 256 threads per block -> 4 rows, 64 threads per row.
// ---------------------------------------------------------------------------
__global__ __launch_bounds__(256)
void attn_kernel(const float* __restrict__ qkv, float* __restrict__ out)
{
    __shared__ __align__(16) float s[4][1536];
    __shared__ float sS[4][64];

    const int tid = threadIdx.x;
    const size_t rowBase = (size_t)blockIdx.x * 4;

    // cooperative load of 4 rows x 1536 floats
    const float4* src = (const float4*)(qkv + rowBase * 1536);
    float4* dst = (float4*)&s[0][0];
#pragma unroll
    for (int i = 0; i < 6; i++) dst[tid + 256 * i] = src[tid + 256 * i];
    __syncthreads();

    const int r  = tid >> 6;   // 0..3
    const int j  = tid & 63;   // 0..63
    const int qh = j >> 3;
    const int kh = j & 7;

    const float* q = &s[r][0];
    const float* k = &s[r][512];
    const float* v = &s[r][1024];

    // scores: 64 (qh,kh) pairs per row
    float sc = 0.f;
#pragma unroll
    for (int c = 0; c < 64; c++) sc += q[qh * 64 + c] * k[kh * 64 + c];
    sS[r][j] = sc * 0.125f;   // (64^-1/4)^2 applied to q and k
    __syncthreads();

    // softmax over kh (8 threads per row do one qh each)
    if (j < 8) {
        float* w = &sS[r][j * 8];
        float mx = w[0];
#pragma unroll
        for (int i = 1; i < 8; i++) mx = fmaxf(mx, w[i]);
        float e[8];
        float sum = 0.f;
#pragma unroll
        for (int i = 0; i < 8; i++) { e[i] = __expf(w[i] - mx); sum += e[i]; }
        float inv = 1.f / sum;
#pragma unroll
        for (int i = 0; i < 8; i++) w[i] = e[i] * inv;
    }
    __syncthreads();

    // attn output: thread (r, j) computes channels [qh*64 + (j&7)*8 .. +8)
    const int cb = (j & 7) * 8;
    float o[8];
#pragma unroll
    for (int i = 0; i < 8; i++) {
        float t = 0.f;
#pragma unroll
        for (int kh2 = 0; kh2 < 8; kh2++)
            t += sS[r][qh * 8 + kh2] * v[kh2 * 64 + cb + i];
        o[i] = t;
    }
    float* orow = out + (rowBase + r) * 512 + qh * 64 + cb;
#pragma unroll
    for (int i = 0; i < 8; i += 4)
        *(float4*)(orow + i) = make_float4(o[i], o[i + 1], o[i + 2], o[i + 3]);
}

// ---------------------------------------------------------------------------
extern "C" void kernel_launch(void* const* d_in, const int* in_sizes, int n_in,
                              void* d_out, int out_size)
{
    const float* x      = (const float*)d_in[0];
    const float* t      = (const float*)d_in[1];
    const float* W_down = (const float*)d_in[2];
    const float* b_down = (const float*)d_in[3];
    const float* W_t    = (const float*)d_in[4];
    const float* b_t    = (const float*)d_in[5];
    const float* W_qkv  = (const float*)d_in[6];
    const float* b_qkv  = (const float*)d_in[7];
    const float* W_out  = (const float*)d_in[8];
    const float* b_out  = (const float*)d_in[9];
    float* out = (float*)d_out;

    void* p;
    float *temb, *x2, *qkv, *attn;
    cudaGetSymbolAddress(&p, g_temb); temb = (float*)p;
    cudaGetSymbolAddress(&p, g_x2);   x2   = (float*)p;
    cudaGetSymbolAddress(&p, g_qkv);  qkv  = (float*)p;
    cudaGetSymbolAddress(&p, g_attn); attn = (float*)p;

    dim3 blk(256);
    // 1) time embedding: temb = t @ W_t^T + b_t            [8192, 512]
    gemm_kernel<0><<<dim3(4, 64), blk>>>(t, W_t, b_t, nullptr, temb,
                                         BSZ, OUT_CH, T_DIM);
    // 2) x2 = x @ W_down^T + b_down + temb[row>>3]         [65536, 512]
    gemm_kernel<1><<<dim3(4, 512), blk>>>(x, W_down, b_down, temb, x2,
                                          ROWS, OUT_CH, IN_CH);
    // 3) qkv = x2 @ W_qkv^T + b_qkv                        [65536, 1536]
    gemm_kernel<0><<<dim3(12, 512), blk>>>(x2, W_qkv, b_qkv, nullptr, qkv,
                                           ROWS, 3 * OUT_CH, OUT_CH);
    // 4) per-row head-softmax attention                    [65536, 512]
    attn_kernel<<<ROWS / 4, blk>>>(qkv, attn);
    // 5) out = attn @ W_out^T + b_out                      [65536, 512]
    gemm_kernel<0><<<dim3(4, 512), blk>>>(attn, W_out, b_out, nullptr, out,
                                          ROWS, OUT_CH, OUT_CH);
}

// round 3
// speedup vs baseline: 4.7300x; 4.7300x over previous
#include <cuda_runtime.h>
#include <cuda_bf16.h>
#include <cstdint>
#include <cstddef>

// ---------------------------------------------------------------------------
// TSABlock via bf16 mma.sync (sm_80-class HMMA; tcgen05 unavailable because
// the harness PTX targets compute_103 without the 'a' feature set).
// All GEMMs: hi/lo-split 3-term bf16 over K' = 3K:
//   A2 = [Ahi | Alo | Ahi], W2 = [Whi | Whi | Wlo]
//   => sum = Ahi*Whi + Alo*Whi + Ahi*Wlo   (dropped lo*lo ~ 2^-18)
// Attention is fully row-local (HEADS==CLIP==8 torch-.view quirk).
// ---------------------------------------------------------------------------

#define BSZ     8192
#define IN_CH   1024
#define OUT_CH  512
#define T_DIM   512
#define ROWS    65536           // BSZ * CLIP

// ---------------- device-global scratch (no runtime allocs) ----------------
__device__ __nv_bfloat16 g_t2  [(size_t)BSZ  * 3 * T_DIM];
__device__ __nv_bfloat16 g_x2a [(size_t)ROWS * 3 * IN_CH];
__device__ __nv_bfloat16 g_wd2 [(size_t)OUT_CH * 3 * IN_CH];
__device__ __nv_bfloat16 g_wt2 [(size_t)OUT_CH * 3 * T_DIM];
__device__ __nv_bfloat16 g_wq2 [(size_t)3 * OUT_CH * 3 * OUT_CH];
__device__ __nv_bfloat16 g_wo2 [(size_t)OUT_CH * 3 * OUT_CH];
__device__ float         g_temb[(size_t)BSZ * OUT_CH];
__device__ __nv_bfloat16 g_h2  [(size_t)ROWS * 3 * OUT_CH];
__device__ float         g_qkv [(size_t)ROWS * 3 * OUT_CH];
__device__ __nv_bfloat16 g_at2 [(size_t)ROWS * 3 * OUT_CH];

// ---------------------------- helpers --------------------------------------
__device__ __forceinline__ uint32_t smem_u32(const void* p) {
    uint32_t a;
    asm("{ .reg .u64 t; cvta.to.shared.u64 t, %1; cvt.u32.u64 %0, t; }"
        : "=r"(a) : "l"(p));
    return a;
}
__device__ __forceinline__ void ldsm4(uint32_t* r, uint32_t addr) {
    asm volatile("ldmatrix.sync.aligned.m8n8.x4.shared.b16 {%0,%1,%2,%3}, [%4];"
                 : "=r"(r[0]), "=r"(r[1]), "=r"(r[2]), "=r"(r[3]) : "r"(addr));
}
__device__ __forceinline__ void mma16816(float* d, const uint32_t* a,
                                         uint32_t b0, uint32_t b1) {
    asm volatile("mma.sync.aligned.m16n8k16.row.col.f32.bf16.bf16.f32 "
                 "{%0,%1,%2,%3}, {%4,%5,%6,%7}, {%8,%9}, {%0,%1,%2,%3};"
                 : "+f"(d[0]), "+f"(d[1]), "+f"(d[2]), "+f"(d[3])
                 : "r"(a[0]), "r"(a[1]), "r"(a[2]), "r"(a[3]), "r"(b0), "r"(b1));
}
#define CP_ASYNC(dst, src) \
    asm volatile("cp.async.cg.shared.global [%0], [%1], 16;" :: "r"(dst), "l"(src))
#define CP_COMMIT() asm volatile("cp.async.commit_group;" ::: "memory")
#define CP_WAIT(n)  asm volatile("cp.async.wait_group %0;" :: "n"(n) : "memory")

__device__ __forceinline__ uint32_t pk2bf(__nv_bfloat16 a, __nv_bfloat16 b) {
    return (uint32_t)__bfloat16_as_ushort(a) | ((uint32_t)__bfloat16_as_ushort(b) << 16);
}
__device__ __forceinline__ void split_bf(float v, __nv_bfloat16& h, __nv_bfloat16& l) {
    h = __float2bfloat16_rn(v);
    l = __float2bfloat16_rn(v - __bfloat162float(h));
}

// ---------------------------------------------------------------------------
// conv_split: fp32 [M,K] -> bf16 [M,3K]; loSeg = 1 (activations) or 2 (weights)
// ---------------------------------------------------------------------------
__global__ void conv_split(const float4* __restrict__ in, __nv_bfloat16* __restrict__ out,
                           int k4, int K, int loSeg, long total4)
{
    long idx = (long)blockIdx.x * blockDim.x + threadIdx.x;
    if (idx >= total4) return;
    long r = idx / k4;
    int  c = (int)(idx - r * k4);
    float4 v = in[idx];
    __nv_bfloat16 h0, h1, h2, h3, l0, l1, l2, l3;
    split_bf(v.x, h0, l0); split_bf(v.y, h1, l1);
    split_bf(v.z, h2, l2); split_bf(v.w, h3, l3);
    uint2 hv = make_uint2(pk2bf(h0, h1), pk2bf(h2, h3));
    uint2 lv = make_uint2(pk2bf(l0, l1), pk2bf(l2, l3));
    __nv_bfloat16* base = out + r * (3L * K) + c * 4;
    *(uint2*)(base)         = hv;
    *(uint2*)(base + K)     = (loSeg == 1) ? lv : hv;
    *(uint2*)(base + 2 * K) = (loSeg == 2) ? lv : hv;
}

// ---------------------------------------------------------------------------
// GEMM: C[M,N] = A[M,K2] @ W[N,K2]^T + bias (+extra for MODE 1)
// Block 128x128, BK=32 bf16, 8 warps (2m x 4n), warp tile 64x32.
// 4-stage cp.async pipeline; smem rows 64B, xor swizzle c ^= (row>>1)&3.
// MODE 0: fp32 out [*,N].   MODE 1: hi/lo-split bf16 out (row stride 1536).
// ---------------------------------------------------------------------------
#define STAGES      4
#define STAGE_BYTES 16384    // A 8KB + B 8KB

template <int MODE>
__global__ __launch_bounds__(256, 2)
void gemm_mma(const __nv_bfloat16* __restrict__ A, const __nv_bfloat16* __restrict__ B,
              const float* __restrict__ bias, const float* __restrict__ extra,
              void* __restrict__ Cout, int N, int K2)
{
    extern __shared__ char sm[];
    const uint32_t smemBase = smem_u32(sm);
    const int tid    = threadIdx.x;
    const int lane   = tid & 31;
    const int wid    = tid >> 5;
    const int warp_m = wid >> 2;       // 0..1
    const int warp_n = wid & 3;        // 0..3
    const int mB     = blockIdx.y * 128;
    const int nB     = blockIdx.x * 128;

    // cp.async slots: 1024 16B-chunks per stage (A 512 + B 512), 4 per thread
    uint32_t dstOff[4];
    const __nv_bfloat16* gsrc[4];
#pragma unroll
    for (int j = 0; j < 4; j++) {
        int chunk = tid + 256 * j;           // 0..1023
        int isB   = chunk >> 9;
        int cc    = chunk & 511;
        int row   = cc >> 2, c = cc & 3;
        dstOff[j] = isB * 8192 + row * 64 + ((c ^ ((row >> 1) & 3)) << 4);
        const __nv_bfloat16* base =
            isB ? B + (size_t)(nB + row) * K2 : A + (size_t)(mB + row) * K2;
        gsrc[j] = base + c * 8;
    }

    // ldmatrix base addresses (stage 0)
    const int la = lane & 15, ha = lane >> 4;
    uint32_t baseA[4];
#pragma unroll
    for (int mi = 0; mi < 4; mi++) {
        int row = warp_m * 64 + mi * 16 + la;
        baseA[mi] = smemBase + row * 64 + ((ha ^ ((row >> 1) & 3)) << 4);
    }
    const int lb = (lane & 7) + ((lane >> 4) << 3);
    const int hb = (lane >> 3) & 1;
    uint32_t baseB[2];
#pragma unroll
    for (int n2 = 0; n2 < 2; n2++) {
        int row = warp_n * 32 + n2 * 16 + lb;
        baseB[n2] = smemBase + 8192 + row * 64 + ((hb ^ ((row >> 1) & 3)) << 4);
    }

    float acc[4][4][4];
#pragma unroll
    for (int mi = 0; mi < 4; mi++)
#pragma unroll
        for (int ni = 0; ni < 4; ni++)
#pragma unroll
            for (int e = 0; e < 4; e++) acc[mi][ni][e] = 0.f;

    const int nIter = K2 >> 5;

    // prologue: fill 3 stages
#pragma unroll
    for (int s = 0; s < STAGES - 1; s++) {
#pragma unroll
        for (int j = 0; j < 4; j++)
            CP_ASYNC(smemBase + s * STAGE_BYTES + dstOff[j], gsrc[j] + s * 32);
        CP_COMMIT();
    }

    for (int it = 0; it < nIter; it++) {
        CP_WAIT(STAGES - 2);
        __syncthreads();

        if (it + STAGES - 1 < nIter) {
            const int s  = (it + STAGES - 1) & (STAGES - 1);
            const int ko = (it + STAGES - 1) * 32;
#pragma unroll
            for (int j = 0; j < 4; j++)
                CP_ASYNC(smemBase + s * STAGE_BYTES + dstOff[j], gsrc[j] + ko);
        }
        CP_COMMIT();

        const uint32_t stOff = (uint32_t)(it & (STAGES - 1)) * STAGE_BYTES;
#pragma unroll
        for (int kk = 0; kk < 2; kk++) {
            uint32_t a[4][4], b[2][4];
#pragma unroll
            for (int mi = 0; mi < 4; mi++)
                ldsm4(a[mi], (baseA[mi] + stOff) ^ (kk << 5));
#pragma unroll
            for (int n2 = 0; n2 < 2; n2++)
                ldsm4(b[n2], (baseB[n2] + stOff) ^ (kk << 5));
#pragma unroll
            for (int mi = 0; mi < 4; mi++)
#pragma unroll
                for (int ni = 0; ni < 4; ni++)
                    mma16816(acc[mi][ni], a[mi],
                             b[ni >> 1][(ni & 1) * 2], b[ni >> 1][(ni & 1) * 2 + 1]);
        }
    }

    // ---------------- epilogue ----------------
    const int mWarp = mB + warp_m * 64;
    const int nWarp = nB + warp_n * 32;
#pragma unroll
    for (int mi = 0; mi < 4; mi++) {
#pragma unroll
        for (int ni = 0; ni < 4; ni++) {
            const int row0 = mWarp + mi * 16 + (lane >> 2);
            const int col  = nWarp + ni * 8 + (lane & 3) * 2;
            const float b0 = __ldg(bias + col);
            const float b1 = __ldg(bias + col + 1);
            float v0 = acc[mi][ni][0] + b0, v1 = acc[mi][ni][1] + b1;
            float v2 = acc[mi][ni][2] + b0, v3 = acc[mi][ni][3] + b1;
            if (MODE == 1) {
                const float* e0 = extra + (size_t)(row0 >> 3) * OUT_CH + col;
                const float* e1 = extra + (size_t)((row0 + 8) >> 3) * OUT_CH + col;
                v0 += __ldg(e0); v1 += __ldg(e0 + 1);
                v2 += __ldg(e1); v3 += __ldg(e1 + 1);
            }
            if (MODE == 0) {
                float* c0 = (float*)Cout + (size_t)row0 * N + col;
                float* c1 = (float*)Cout + (size_t)(row0 + 8) * N + col;
                *(float2*)c0 = make_float2(v0, v1);
                *(float2*)c1 = make_float2(v2, v3);
            } else {
                __nv_bfloat16 h0, l0, h1, l1, h2, l2, h3, l3;
                split_bf(v0, h0, l0); split_bf(v1, h1, l1);
                split_bf(v2, h2, l2); split_bf(v3, h3, l3);
                __nv_bfloat16* o0 = (__nv_bfloat16*)Cout + (size_t)row0 * 1536 + col;
                __nv_bfloat16* o1 = (__nv_bfloat16*)Cout + (size_t)(row0 + 8) * 1536 + col;
                *(uint32_t*)(o0)        = pk2bf(h0, h1);
                *(uint32_t*)(o0 + 512)  = pk2bf(l0, l1);
                *(uint32_t*)(o0 + 1024) = pk2bf(h0, h1);
                *(uint32_t*)(o1)        = pk2bf(h2, h3);
                *(uint32_t*)(o1 + 512)  = pk2bf(l2, l3);
                *(uint32_t*)(o1 + 1024) = pk2bf(h2, h3);
            }
        }
    }
}

// ---------------------------------------------------------------------------
// Per-row attention (row-local 8x8 head softmax), bank-conflict-free,
// writes hi/lo-split bf16 [hi|lo|hi] rows of 1536.
// ---------------------------------------------------------------------------
__global__ __launch_bounds__(256)
void attn_kernel(const float* __restrict__ qkv, __nv_bfloat16* __restrict__ out2)
{
    __shared__ __align__(16) float sq[4][512];
    __shared__ __align__(16) float sk[4][512];
    __shared__ __align__(16) float sv[4][8 * 68];   // V rows padded to 68 floats
    __shared__ float sS[4][64];

    const int tid = threadIdx.x;
    const size_t rowBase = (size_t)blockIdx.x * 4;

    // cooperative load: 1536 float4 total
    const float4* src = (const float4*)(qkv + rowBase * 1536);
#pragma unroll
    for (int i = 0; i < 6; i++) {
        int idx = tid + 256 * i;            // 0..1535
        int r = idx / 384, f = idx - r * 384;
        float4 v = src[idx];
        if (f < 128)       ((float4*)sq[r])[f] = v;
        else if (f < 256)  ((float4*)sk[r])[f - 128] = v;
        else {
            int f2 = f - 256, kh = f2 >> 4, c4 = f2 & 15;
            *(float4*)&sv[r][kh * 68 + c4 * 4] = v;
        }
    }
    __syncthreads();

    const int r  = tid >> 6;
    const int j  = tid & 63;
    const int qh = j >> 3;
    const int kh = j & 7;

    // scores with lane-rotated k chunks (conflict-free)
    const float4* q4 = (const float4*)&sq[r][qh * 64];
    float sc = 0.f;
#pragma unroll
    for (int i = 0; i < 16; i++) {
        int c4 = (kh + i) & 15;
        float4 a = q4[c4];
        float4 b = *(const float4*)&sk[r][kh * 64 + c4 * 4];
        sc += a.x * b.x + a.y * b.y + a.z * b.z + a.w * b.w;
    }
    sS[r][j] = sc * 0.125f;
    __syncthreads();

    if (j < 8) {
        float* w = &sS[r][j * 8];
        float mx = w[0];
#pragma unroll
        for (int i = 1; i < 8; i++) mx = fmaxf(mx, w[i]);
        float e[8]; float sum = 0.f;
#pragma unroll
        for (int i = 0; i < 8; i++) { e[i] = __expf(w[i] - mx); sum += e[i]; }
        float inv = 1.f / sum;
#pragma unroll
        for (int i = 0; i < 8; i++) w[i] = e[i] * inv;
    }
    __syncthreads();

    const int cb = (j & 7) * 8;
    float o[8];
#pragma unroll
    for (int i = 0; i < 8; i++) o[i] = 0.f;
#pragma unroll
    for (int kk = 0; kk < 8; kk++) {
        int kh2 = (kk + (j & 7)) & 7;       // lane rotation -> no bank conflict
        float w = sS[r][qh * 8 + kh2];
        float4 v0 = *(const float4*)&sv[r][kh2 * 68 + cb];
        float4 v1 = *(const float4*)&sv[r][kh2 * 68 + cb + 4];
        o[0] += w * v0.x; o[1] += w * v0.y; o[2] += w * v0.z; o[3] += w * v0.w;
        o[4] += w * v1.x; o[5] += w * v1.y; o[6] += w * v1.z; o[7] += w * v1.w;
    }
    __nv_bfloat16 h[8], l[8];
#pragma unroll
    for (int i = 0; i < 8; i++) split_bf(o[i], h[i], l[i]);
    uint4 hv = make_uint4(pk2bf(h[0], h[1]), pk2bf(h[2], h[3]),
                          pk2bf(h[4], h[5]), pk2bf(h[6], h[7]));
    uint4 lv = make_uint4(pk2bf(l[0], l[1]), pk2bf(l[2], l[3]),
                          pk2bf(l[4], l[5]), pk2bf(l[6], l[7]));
    __nv_bfloat16* base = out2 + (rowBase + r) * 1536 + qh * 64 + cb;
    *(uint4*)(base)        = hv;
    *(uint4*)(base + 512)  = lv;
    *(uint4*)(base + 1024) = hv;
}

// ---------------------------------------------------------------------------
extern "C" void kernel_launch(void* const* d_in, const int* in_sizes, int n_in,
                              void* d_out, int out_size)
{
    const float* x      = (const float*)d_in[0];
    const float* t      = (const float*)d_in[1];
    const float* W_down = (const float*)d_in[2];
    const float* b_down = (const float*)d_in[3];
    const float* W_t    = (const float*)d_in[4];
    const float* b_t    = (const float*)d_in[5];
    const float* W_qkv  = (const float*)d_in[6];
    const float* b_qkv  = (const float*)d_in[7];
    const float* W_out  = (const float*)d_in[8];
    const float* b_out  = (const float*)d_in[9];
    float* out = (float*)d_out;

    void* p;
    __nv_bfloat16 *t2, *x2a, *wd2, *wt2, *wq2, *wo2, *h2, *at2;
    float *temb, *qkv;
    cudaGetSymbolAddress(&p, g_t2);   t2  = (__nv_bfloat16*)p;
    cudaGetSymbolAddress(&p, g_x2a);  x2a = (__nv_bfloat16*)p;
    cudaGetSymbolAddress(&p, g_wd2);  wd2 = (__nv_bfloat16*)p;
    cudaGetSymbolAddress(&p, g_wt2);  wt2 = (__nv_bfloat16*)p;
    cudaGetSymbolAddress(&p, g_wq2);  wq2 = (__nv_bfloat16*)p;
    cudaGetSymbolAddress(&p, g_wo2);  wo2 = (__nv_bfloat16*)p;
    cudaGetSymbolAddress(&p, g_temb); temb = (float*)p;
    cudaGetSymbolAddress(&p, g_h2);   h2  = (__nv_bfloat16*)p;
    cudaGetSymbolAddress(&p, g_qkv);  qkv = (float*)p;
    cudaGetSymbolAddress(&p, g_at2);  at2 = (__nv_bfloat16*)p;

    const int dynSmem = STAGES * STAGE_BYTES;   // 64 KB
    cudaFuncSetAttribute(gemm_mma<0>, cudaFuncAttributeMaxDynamicSharedMemorySize, dynSmem);
    cudaFuncSetAttribute(gemm_mma<1>, cudaFuncAttributeMaxDynamicSharedMemorySize, dynSmem);

    auto conv = [&](const float* in, __nv_bfloat16* o, long M, int K, int loSeg) {
        long total4 = M * K / 4;
        int blocks = (int)((total4 + 255) / 256);
        conv_split<<<blocks, 256>>>((const float4*)in, o, K / 4, K, loSeg, total4);
    };

    conv(W_t,    wt2, OUT_CH,     T_DIM,  2);
    conv(W_down, wd2, OUT_CH,     IN_CH,  2);
    conv(W_qkv,  wq2, 3 * OUT_CH, OUT_CH, 2);
    conv(W_out,  wo2, OUT_CH,     OUT_CH, 2);
    conv(t,      t2,  BSZ,        T_DIM,  1);
    conv(x,      x2a, ROWS,       IN_CH,  1);

    // 1) temb = t @ W_t^T + b_t                         [8192, 512] fp32
    gemm_mma<0><<<dim3(4, 64), 256, dynSmem>>>(t2, wt2, b_t, nullptr, temb,
                                               OUT_CH, 3 * T_DIM);
    // 2) x2 = x @ W_down^T + b_down + temb -> split     [65536 -> 1536 bf16]
    gemm_mma<1><<<dim3(4, 512), 256, dynSmem>>>(x2a, wd2, b_down, temb, h2,
                                                OUT_CH, 3 * IN_CH);
    // 3) qkv = x2 @ W_qkv^T + b_qkv                     [65536, 1536] fp32
    gemm_mma<0><<<dim3(12, 512), 256, dynSmem>>>(h2, wq2, b_qkv, nullptr, qkv,
                                                 3 * OUT_CH, 3 * OUT_CH);
    // 4) attention -> split                             [65536 -> 1536 bf16]
    attn_kernel<<<ROWS / 4, 256>>>(qkv, at2);
    // 5) out = attn @ W_out^T + b_out                   [65536, 512] fp32
    gemm_mma<0><<<dim3(4, 512), 256, dynSmem>>>(at2, wo2, b_out, nullptr, out,
                                                OUT_CH, 3 * OUT_CH);
}

// round 4
// speedup vs baseline: 5.1357x; 1.0858x over previous
#include <cuda_runtime.h>
#include <cuda_bf16.h>
#include <cstdint>
#include <cstddef>

// ---------------------------------------------------------------------------
// TSABlock via bf16 mma.sync HMMA (tcgen05 blocked: harness PTX = compute_103,
// no 'a' feature set). 3-term hi/lo split GEMMs:
//   sum = Ahi*Whi + Alo*Whi + Ahi*Wlo
// Activations stored [hi|lo] (2K); third segment remapped to seg 0 in-GEMM.
// Weights stored [hi|hi|lo] (3K). Attention is row-local (HEADS==CLIP==8).
// ---------------------------------------------------------------------------

#define BSZ     8192
#define IN_CH   1024
#define OUT_CH  512
#define T_DIM   512
#define ROWS    65536

__device__ __nv_bfloat16 g_t2  [(size_t)BSZ  * 2 * T_DIM];
__device__ __nv_bfloat16 g_x2a [(size_t)ROWS * 2 * IN_CH];
__device__ __nv_bfloat16 g_wd2 [(size_t)OUT_CH * 3 * IN_CH];
__device__ __nv_bfloat16 g_wt2 [(size_t)OUT_CH * 3 * T_DIM];
__device__ __nv_bfloat16 g_wq2 [(size_t)3 * OUT_CH * 3 * OUT_CH];
__device__ __nv_bfloat16 g_wo2 [(size_t)OUT_CH * 3 * OUT_CH];
__device__ float         g_temb[(size_t)BSZ * OUT_CH];
__device__ __nv_bfloat16 g_h2  [(size_t)ROWS * 2 * OUT_CH];
__device__ float         g_qkv [(size_t)ROWS * 3 * OUT_CH];
__device__ __nv_bfloat16 g_at2 [(size_t)ROWS * 2 * OUT_CH];

// ---------------------------- helpers --------------------------------------
__device__ __forceinline__ uint32_t smem_u32(const void* p) {
    uint32_t a;
    asm("{ .reg .u64 t; cvta.to.shared.u64 t, %1; cvt.u32.u64 %0, t; }"
        : "=r"(a) : "l"(p));
    return a;
}
__device__ __forceinline__ void ldsm4(uint32_t* r, uint32_t addr) {
    asm volatile("ldmatrix.sync.aligned.m8n8.x4.shared.b16 {%0,%1,%2,%3}, [%4];"
                 : "=r"(r[0]), "=r"(r[1]), "=r"(r[2]), "=r"(r[3]) : "r"(addr));
}
__device__ __forceinline__ void mma16816(float* d, const uint32_t* a,
                                         uint32_t b0, uint32_t b1) {
    asm volatile("mma.sync.aligned.m16n8k16.row.col.f32.bf16.bf16.f32 "
                 "{%0,%1,%2,%3}, {%4,%5,%6,%7}, {%8,%9}, {%0,%1,%2,%3};"
                 : "+f"(d[0]), "+f"(d[1]), "+f"(d[2]), "+f"(d[3])
                 : "r"(a[0]), "r"(a[1]), "r"(a[2]), "r"(a[3]), "r"(b0), "r"(b1));
}
#define CP_ASYNC(dst, src) \
    asm volatile("cp.async.cg.shared.global [%0], [%1], 16;" :: "r"(dst), "l"(src))
#define CP_COMMIT() asm volatile("cp.async.commit_group;" ::: "memory")
#define CP_WAIT(n)  asm volatile("cp.async.wait_group %0;" :: "n"(n) : "memory")

__device__ __forceinline__ uint32_t pk2bf(__nv_bfloat16 a, __nv_bfloat16 b) {
    return (uint32_t)__bfloat16_as_ushort(a) | ((uint32_t)__bfloat16_as_ushort(b) << 16);
}
__device__ __forceinline__ void split_bf(float v, __nv_bfloat16& h, __nv_bfloat16& l) {
    h = __float2bfloat16_rn(v);
    l = __float2bfloat16_rn(v - __bfloat162float(h));
}

// ---------------------------------------------------------------------------
// conv_act: fp32 [M,K] -> bf16 [M,2K] = [hi|lo]
// ---------------------------------------------------------------------------
__global__ void conv_act(const float4* __restrict__ in, __nv_bfloat16* __restrict__ out,
                         int k4, int K, long total4)
{
    long idx = (long)blockIdx.x * blockDim.x + threadIdx.x;
    if (idx >= total4) return;
    long r = idx / k4;
    int  c = (int)(idx - r * k4);
    float4 v = in[idx];
    __nv_bfloat16 h0, h1, h2, h3, l0, l1, l2, l3;
    split_bf(v.x, h0, l0); split_bf(v.y, h1, l1);
    split_bf(v.z, h2, l2); split_bf(v.w, h3, l3);
    __nv_bfloat16* base = out + r * (2L * K) + c * 4;
    *(uint2*)(base)     = make_uint2(pk2bf(h0, h1), pk2bf(h2, h3));
    *(uint2*)(base + K) = make_uint2(pk2bf(l0, l1), pk2bf(l2, l3));
}

// ---------------------------------------------------------------------------
// conv_w_all: all 4 weight tensors -> bf16 [N,3K] = [hi|hi|lo], one launch.
// float4 regions: W_down 131072 | W_t 65536 | W_qkv 196608 | W_out 65536
// ---------------------------------------------------------------------------
__global__ void conv_w_all(const float4* __restrict__ wd, const float4* __restrict__ wt,
                           const float4* __restrict__ wq, const float4* __restrict__ wo,
                           __nv_bfloat16* __restrict__ od, __nv_bfloat16* __restrict__ ot,
                           __nv_bfloat16* __restrict__ oq, __nv_bfloat16* __restrict__ oo)
{
    long idx = (long)blockIdx.x * blockDim.x + threadIdx.x;
    const float4* in; __nv_bfloat16* out; int k4; long lidx;
    if (idx < 131072)       { in = wd; out = od; k4 = 256; lidx = idx; }
    else if (idx < 196608)  { in = wt; out = ot; k4 = 128; lidx = idx - 131072; }
    else if (idx < 393216)  { in = wq; out = oq; k4 = 128; lidx = idx - 196608; }
    else if (idx < 458752)  { in = wo; out = oo; k4 = 128; lidx = idx - 393216; }
    else return;
    int K = k4 * 4;
    long r = lidx / k4;
    int  c = (int)(lidx - r * k4);
    float4 v = in[lidx];
    __nv_bfloat16 h0, h1, h2, h3, l0, l1, l2, l3;
    split_bf(v.x, h0, l0); split_bf(v.y, h1, l1);
    split_bf(v.z, h2, l2); split_bf(v.w, h3, l3);
    uint2 hv = make_uint2(pk2bf(h0, h1), pk2bf(h2, h3));
    uint2 lv = make_uint2(pk2bf(l0, l1), pk2bf(l2, l3));
    __nv_bfloat16* base = out + r * (3L * K) + c * 4;
    *(uint2*)(base)         = hv;
    *(uint2*)(base + K)     = hv;
    *(uint2*)(base + 2 * K) = lv;
}

// ---------------------------------------------------------------------------
// GEMM: C[M,N] = A[M,2K]~(3K view) @ W[N,3K]^T + bias (+extra, MODE 1)
// Block 128x128, BK=64, 3-stage cp.async, 8 warps (2m x 4n), warp 64x32.
// Smem rows 128B, canonical SW128 swizzle (chunk ^= row&7).
// A k-segment remap: iter >= aWrap reads iter-aWrap (hi again).
// MODE 0: fp32 out [*,N].  MODE 1: [hi|lo] bf16 out, row stride 1024.
// ---------------------------------------------------------------------------
#define STAGES      3
#define STAGE_BYTES 32768    // A 16KB + B 16KB

template <int MODE>
__global__ __launch_bounds__(256, 2)
void gemm_mma(const __nv_bfloat16* __restrict__ A, const __nv_bfloat16* __restrict__ B,
              const float* __restrict__ bias, const float* __restrict__ extra,
              void* __restrict__ Cout, int N, int K2, int strideA, int aWrap)
{
    extern __shared__ char sm[];
    const uint32_t smemBase = smem_u32(sm);
    const int tid    = threadIdx.x;
    const int lane   = tid & 31;
    const int wid    = tid >> 5;
    const int warp_m = wid >> 2;
    const int warp_n = wid & 3;
    const int mB     = blockIdx.y * 128;
    const int nB     = blockIdx.x * 128;

    // cp.async: 2048 16B chunks/stage (A 1024 + B 1024), 8 per thread
    uint32_t dstOff[8];
    const __nv_bfloat16* gsrc[8];
#pragma unroll
    for (int j = 0; j < 8; j++) {
        int chunk = tid + 256 * j;
        int isB   = chunk >> 10;
        int cc    = chunk & 1023;
        int row   = cc >> 3, c = cc & 7;
        dstOff[j] = isB * 16384 + row * 128 + ((c ^ (row & 7)) << 4);
        gsrc[j] = (isB ? B + (size_t)(nB + row) * K2
                       : A + (size_t)(mB + row) * strideA) + c * 8;
    }

    // ldmatrix bases (stage 0, k-chunk 0)
    const int la = lane & 15, ha = lane >> 4;
    uint32_t baseA[4];
#pragma unroll
    for (int mi = 0; mi < 4; mi++) {
        int row = warp_m * 64 + mi * 16 + la;
        baseA[mi] = smemBase + row * 128 + ((ha ^ (row & 7)) << 4);
    }
    const int lb = (lane & 7) + ((lane >> 4) << 3);
    const int hb = (lane >> 3) & 1;
    uint32_t baseB[2];
#pragma unroll
    for (int n2 = 0; n2 < 2; n2++) {
        int row = warp_n * 32 + n2 * 16 + lb;
        baseB[n2] = smemBase + 16384 + row * 128 + ((hb ^ (row & 7)) << 4);
    }

    float acc[4][4][4];
#pragma unroll
    for (int mi = 0; mi < 4; mi++)
#pragma unroll
        for (int ni = 0; ni < 4; ni++)
#pragma unroll
            for (int e = 0; e < 4; e++) acc[mi][ni][e] = 0.f;

    const int nIter = K2 >> 6;

    // prologue: 2 stages
#pragma unroll
    for (int s = 0; s < STAGES - 1; s++) {
#pragma unroll
        for (int j = 0; j < 8; j++) {
            int ko = (j < 4 ? (s >= aWrap ? s - aWrap : s) : s) * 64;
            CP_ASYNC(smemBase + s * STAGE_BYTES + dstOff[j], gsrc[j] + ko);
        }
        CP_COMMIT();
    }

    int stage = 0;
    for (int it = 0; it < nIter; it++) {
        CP_WAIT(1);
        __syncthreads();

        if (it + STAGES - 1 < nIter) {
            const int pit = it + STAGES - 1;
            const int pstage = (stage + STAGES - 1 >= STAGES) ? stage - 1 : stage + 2;
            const int aoff = (pit >= aWrap ? pit - aWrap : pit) * 64;
            const int boff = pit * 64;
#pragma unroll
            for (int j = 0; j < 8; j++)
                CP_ASYNC(smemBase + pstage * STAGE_BYTES + dstOff[j],
                         gsrc[j] + (j < 4 ? aoff : boff));
        }
        CP_COMMIT();

        const uint32_t stOff = (uint32_t)stage * STAGE_BYTES;
#pragma unroll
        for (int kk = 0; kk < 4; kk++) {
            uint32_t a[4][4], b[2][4];
#pragma unroll
            for (int mi = 0; mi < 4; mi++)
                ldsm4(a[mi], (baseA[mi] + stOff) ^ (kk << 5));
#pragma unroll
            for (int n2 = 0; n2 < 2; n2++)
                ldsm4(b[n2], (baseB[n2] + stOff) ^ (kk << 5));
#pragma unroll
            for (int mi = 0; mi < 4; mi++)
#pragma unroll
                for (int ni = 0; ni < 4; ni++)
                    mma16816(acc[mi][ni], a[mi],
                             b[ni >> 1][(ni & 1) * 2], b[ni >> 1][(ni & 1) * 2 + 1]);
        }
        stage = (stage + 1 == STAGES) ? 0 : stage + 1;
    }

    // ---------------- epilogue ----------------
    const int mWarp = mB + warp_m * 64;
    const int nWarp = nB + warp_n * 32;
#pragma unroll
    for (int mi = 0; mi < 4; mi++) {
#pragma unroll
        for (int ni = 0; ni < 4; ni++) {
            const int row0 = mWarp + mi * 16 + (lane >> 2);
            const int col  = nWarp + ni * 8 + (lane & 3) * 2;
            const float b0 = __ldg(bias + col);
            const float b1 = __ldg(bias + col + 1);
            float v0 = acc[mi][ni][0] + b0, v1 = acc[mi][ni][1] + b1;
            float v2 = acc[mi][ni][2] + b0, v3 = acc[mi][ni][3] + b1;
            if (MODE == 1) {
                const float* e0 = extra + (size_t)(row0 >> 3) * OUT_CH + col;
                const float* e1 = extra + (size_t)((row0 + 8) >> 3) * OUT_CH + col;
                v0 += __ldg(e0); v1 += __ldg(e0 + 1);
                v2 += __ldg(e1); v3 += __ldg(e1 + 1);
            }
            if (MODE == 0) {
                float* c0 = (float*)Cout + (size_t)row0 * N + col;
                float* c1 = (float*)Cout + (size_t)(row0 + 8) * N + col;
                *(float2*)c0 = make_float2(v0, v1);
                *(float2*)c1 = make_float2(v2, v3);
            } else {
                __nv_bfloat16 h0, l0, h1, l1, h2, l2, h3, l3;
                split_bf(v0, h0, l0); split_bf(v1, h1, l1);
                split_bf(v2, h2, l2); split_bf(v3, h3, l3);
                __nv_bfloat16* o0 = (__nv_bfloat16*)Cout + (size_t)row0 * 1024 + col;
                __nv_bfloat16* o1 = (__nv_bfloat16*)Cout + (size_t)(row0 + 8) * 1024 + col;
                *(uint32_t*)(o0)       = pk2bf(h0, h1);
                *(uint32_t*)(o0 + 512) = pk2bf(l0, l1);
                *(uint32_t*)(o1)       = pk2bf(h2, h3);
                *(uint32_t*)(o1 + 512) = pk2bf(l2, l3);
            }
        }
    }
}

// ---------------------------------------------------------------------------
// Per-row attention (row-local 8x8 head softmax), writes [hi|lo] bf16.
// ---------------------------------------------------------------------------
__global__ __launch_bounds__(256)
void attn_kernel(const float* __restrict__ qkv, __nv_bfloat16* __restrict__ out2)
{
    __shared__ __align__(16) float sq[4][512];
    __shared__ __align__(16) float sk[4][512];
    __shared__ __align__(16) float sv[4][8 * 68];
    __shared__ float sS[4][64];

    const int tid = threadIdx.x;
    const size_t rowBase = (size_t)blockIdx.x * 4;

    const float4* src = (const float4*)(qkv + rowBase * 1536);
#pragma unroll
    for (int i = 0; i < 6; i++) {
        int idx = tid + 256 * i;
        int r = idx / 384, f = idx - r * 384;
        float4 v = src[idx];
        if (f < 128)       ((float4*)sq[r])[f] = v;
        else if (f < 256)  ((float4*)sk[r])[f - 128] = v;
        else {
            int f2 = f - 256, kh = f2 >> 4, c4 = f2 & 15;
            *(float4*)&sv[r][kh * 68 + c4 * 4] = v;
        }
    }
    __syncthreads();

    const int r  = tid >> 6;
    const int j  = tid & 63;
    const int qh = j >> 3;
    const int kh = j & 7;

    const float4* q4 = (const float4*)&sq[r][qh * 64];
    float sc = 0.f;
#pragma unroll
    for (int i = 0; i < 16; i++) {
        int c4 = (kh + i) & 15;
        float4 a = q4[c4];
        float4 b = *(const float4*)&sk[r][kh * 64 + c4 * 4];
        sc += a.x * b.x + a.y * b.y + a.z * b.z + a.w * b.w;
    }
    sS[r][j] = sc * 0.125f;
    __syncthreads();

    if (j < 8) {
        float* w = &sS[r][j * 8];
        float mx = w[0];
#pragma unroll
        for (int i = 1; i < 8; i++) mx = fmaxf(mx, w[i]);
        float e[8]; float sum = 0.f;
#pragma unroll
        for (int i = 0; i < 8; i++) { e[i] = __expf(w[i] - mx); sum += e[i]; }
        float inv = 1.f / sum;
#pragma unroll
        for (int i = 0; i < 8; i++) w[i] = e[i] * inv;
    }
    __syncthreads();

    const int cb = (j & 7) * 8;
    float o[8];
#pragma unroll
    for (int i = 0; i < 8; i++) o[i] = 0.f;
#pragma unroll
    for (int kk = 0; kk < 8; kk++) {
        int kh2 = (kk + (j & 7)) & 7;
        float w = sS[r][qh * 8 + kh2];
        float4 v0 = *(const float4*)&sv[r][kh2 * 68 + cb];
        float4 v1 = *(const float4*)&sv[r][kh2 * 68 + cb + 4];
        o[0] += w * v0.x; o[1] += w * v0.y; o[2] += w * v0.z; o[3] += w * v0.w;
        o[4] += w * v1.x; o[5] += w * v1.y; o[6] += w * v1.z; o[7] += w * v1.w;
    }
    __nv_bfloat16 h[8], l[8];
#pragma unroll
    for (int i = 0; i < 8; i++) split_bf(o[i], h[i], l[i]);
    uint4 hv = make_uint4(pk2bf(h[0], h[1]), pk2bf(h[2], h[3]),
                          pk2bf(h[4], h[5]), pk2bf(h[6], h[7]));
    uint4 lv = make_uint4(pk2bf(l[0], l[1]), pk2bf(l[2], l[3]),
                          pk2bf(l[4], l[5]), pk2bf(l[6], l[7]));
    __nv_bfloat16* base = out2 + (rowBase + r) * 1024 + qh * 64 + cb;
    *(uint4*)(base)       = hv;
    *(uint4*)(base + 512) = lv;
}

// ---------------------------------------------------------------------------
extern "C" void kernel_launch(void* const* d_in, const int* in_sizes, int n_in,
                              void* d_out, int out_size)
{
    const float* x      = (const float*)d_in[0];
    const float* t      = (const float*)d_in[1];
    const float* W_down = (const float*)d_in[2];
    const float* b_down = (const float*)d_in[3];
    const float* W_t    = (const float*)d_in[4];
    const float* b_t    = (const float*)d_in[5];
    const float* W_qkv  = (const float*)d_in[6];
    const float* b_qkv  = (const float*)d_in[7];
    const float* W_out  = (const float*)d_in[8];
    const float* b_out  = (const float*)d_in[9];
    float* out = (float*)d_out;

    void* p;
    __nv_bfloat16 *t2, *x2a, *wd2, *wt2, *wq2, *wo2, *h2, *at2;
    float *temb, *qkv;
    cudaGetSymbolAddress(&p, g_t2);   t2  = (__nv_bfloat16*)p;
    cudaGetSymbolAddress(&p, g_x2a);  x2a = (__nv_bfloat16*)p;
    cudaGetSymbolAddress(&p, g_wd2);  wd2 = (__nv_bfloat16*)p;
    cudaGetSymbolAddress(&p, g_wt2);  wt2 = (__nv_bfloat16*)p;
    cudaGetSymbolAddress(&p, g_wq2);  wq2 = (__nv_bfloat16*)p;
    cudaGetSymbolAddress(&p, g_wo2);  wo2 = (__nv_bfloat16*)p;
    cudaGetSymbolAddress(&p, g_temb); temb = (float*)p;
    cudaGetSymbolAddress(&p, g_h2);   h2  = (__nv_bfloat16*)p;
    cudaGetSymbolAddress(&p, g_qkv);  qkv = (float*)p;
    cudaGetSymbolAddress(&p, g_at2);  at2 = (__nv_bfloat16*)p;

    const int dynSmem = STAGES * STAGE_BYTES;   // 96 KB
    cudaFuncSetAttribute(gemm_mma<0>, cudaFuncAttributeMaxDynamicSharedMemorySize, dynSmem);
    cudaFuncSetAttribute(gemm_mma<1>, cudaFuncAttributeMaxDynamicSharedMemorySize, dynSmem);

    // launch 0: all weights            launch 1: t   launch 2: x
    conv_w_all<<<1792, 256>>>((const float4*)W_down, (const float4*)W_t,
                              (const float4*)W_qkv, (const float4*)W_out,
                              wd2, wt2, wq2, wo2);
    conv_act<<<(BSZ * T_DIM / 4 + 255) / 256, 256>>>((const float4*)t, t2,
                                                     T_DIM / 4, T_DIM,
                                                     (long)BSZ * T_DIM / 4);
    conv_act<<<((long)ROWS * IN_CH / 4 + 255) / 256, 256>>>((const float4*)x, x2a,
                                                            IN_CH / 4, IN_CH,
                                                            (long)ROWS * IN_CH / 4);

    // 3: temb = t @ W_t^T + b_t                       [8192, 512] fp32
    gemm_mma<0><<<dim3(4, 64), 256, dynSmem>>>(t2, wt2, b_t, nullptr, temb,
                                               OUT_CH, 3 * T_DIM, 2 * T_DIM, 16);
    // 4: x2 = x @ W_down^T + b_down + temb -> [hi|lo] [65536, 1024 bf16]
    gemm_mma<1><<<dim3(4, 512), 256, dynSmem>>>(x2a, wd2, b_down, temb, h2,
                                                OUT_CH, 3 * IN_CH, 2 * IN_CH, 32);
    // 5: qkv = x2 @ W_qkv^T + b_qkv                   [65536, 1536] fp32  (ncu!)
    gemm_mma<0><<<dim3(12, 512), 256, dynSmem>>>(h2, wq2, b_qkv, nullptr, qkv,
                                                 3 * OUT_CH, 3 * OUT_CH, 2 * OUT_CH, 16);
    // 6: attention -> [hi|lo]
    attn_kernel<<<ROWS / 4, 256>>>(qkv, at2);
    // 7: out = attn @ W_out^T + b_out                 [65536, 512] fp32
    gemm_mma<0><<<dim3(4, 512), 256, dynSmem>>>(at2, wo2, b_out, nullptr, out,
                                                OUT_CH, 3 * OUT_CH, 2 * OUT_CH, 16);
}

// round 7
// speedup vs baseline: 6.9816x; 1.3594x over previous
#include <cuda_runtime.h>
#include <cuda_fp16.h>
#include <cstdint>
#include <cstddef>

// ---------------------------------------------------------------------------
// TSABlock via fp16 mma.sync HMMA (tcgen05 blocked: harness PTX = compute_103).
// 2-term fp16 split GEMMs:  A = Ahi + Alo (fp16 pair, exact to ~2^-22),
// W = single fp16 copy  =>  C = (Ahi + Alo) @ W.  Only error: W fp16 rounding
// (~2.8e-4 rms per GEMM, norm-based metric, threshold 1e-3).
// A stored [hi|lo] (2K); W stored [N,K] fp16 with B-side K-segment wrap.
// Attention is fully row-local (HEADS==CLIP==8 torch-.view quirk).
// ---------------------------------------------------------------------------

#define BSZ     8192
#define IN_CH   1024
#define OUT_CH  512
#define T_DIM   512
#define ROWS    65536

__device__ __half g_t2  [(size_t)BSZ  * 2 * T_DIM];
__device__ __half g_x2a [(size_t)ROWS * 2 * IN_CH];
__device__ __half g_wd2 [(size_t)OUT_CH * IN_CH];
__device__ __half g_wt2 [(size_t)OUT_CH * T_DIM];
__device__ __half g_wq2 [(size_t)3 * OUT_CH * OUT_CH];
__device__ __half g_wo2 [(size_t)OUT_CH * OUT_CH];
__device__ float  g_temb[(size_t)BSZ * OUT_CH];
__device__ __half g_h2  [(size_t)ROWS * 2 * OUT_CH];
__device__ float  g_qkv [(size_t)ROWS * 3 * OUT_CH];
__device__ __half g_at2 [(size_t)ROWS * 2 * OUT_CH];

// ---------------------------- helpers --------------------------------------
__device__ __forceinline__ uint32_t smem_u32(const void* p) {
    uint32_t a;
    asm("{ .reg .u64 t; cvta.to.shared.u64 t, %1; cvt.u32.u64 %0, t; }"
        : "=r"(a) : "l"(p));
    return a;
}
__device__ __forceinline__ void ldsm4(uint32_t* r, uint32_t addr) {
    asm volatile("ldmatrix.sync.aligned.m8n8.x4.shared.b16 {%0,%1,%2,%3}, [%4];"
                 : "=r"(r[0]), "=r"(r[1]), "=r"(r[2]), "=r"(r[3]) : "r"(addr));
}
__device__ __forceinline__ void mma16816(float* d, const uint32_t* a,
                                         uint32_t b0, uint32_t b1) {
    asm volatile("mma.sync.aligned.m16n8k16.row.col.f32.f16.f16.f32 "
                 "{%0,%1,%2,%3}, {%4,%5,%6,%7}, {%8,%9}, {%0,%1,%2,%3};"
                 : "+f"(d[0]), "+f"(d[1]), "+f"(d[2]), "+f"(d[3])
                 : "r"(a[0]), "r"(a[1]), "r"(a[2]), "r"(a[3]), "r"(b0), "r"(b1));
}
#define CP_ASYNC(dst, src) \
    asm volatile("cp.async.cg.shared.global [%0], [%1], 16;" :: "r"(dst), "l"(src))
#define CP_COMMIT() asm volatile("cp.async.commit_group;" ::: "memory")
#define CP_WAIT(n)  asm volatile("cp.async.wait_group %0;" :: "n"(n) : "memory")

__device__ __forceinline__ uint32_t pk2h(__half a, __half b) {
    return (uint32_t)__half_as_ushort(a) | ((uint32_t)__half_as_ushort(b) << 16);
}
__device__ __forceinline__ void split_h(float v, __half& h, __half& l) {
    h = __float2half_rn(v);
    l = __float2half_rn(v - __half2float(h));
}

// ---------------------------------------------------------------------------
// conv_act: fp32 [M,K] -> fp16 [M,2K] = [hi|lo]
// ---------------------------------------------------------------------------
__global__ void conv_act(const float4* __restrict__ in, __half* __restrict__ out,
                         int k4, int K, long total4)
{
    long idx = (long)blockIdx.x * blockDim.x + threadIdx.x;
    if (idx >= total4) return;
    long r = idx / k4;
    int  c = (int)(idx - r * k4);
    float4 v = in[idx];
    __half h0, h1, h2, h3, l0, l1, l2, l3;
    split_h(v.x, h0, l0); split_h(v.y, h1, l1);
    split_h(v.z, h2, l2); split_h(v.w, h3, l3);
    __half* base = out + r * (2L * K) + c * 4;
    *(uint2*)(base)     = make_uint2(pk2h(h0, h1), pk2h(h2, h3));
    *(uint2*)(base + K) = make_uint2(pk2h(l0, l1), pk2h(l2, l3));
}

// ---------------------------------------------------------------------------
// conv_w_all: 4 weight tensors fp32 -> fp16 (plain, elementwise), one launch.
// float4 regions: W_down 131072 | W_t 65536 | W_qkv 196608 | W_out 65536
// ---------------------------------------------------------------------------
__global__ void conv_w_all(const float4* __restrict__ wd, const float4* __restrict__ wt,
                           const float4* __restrict__ wq, const float4* __restrict__ wo,
                           __half* __restrict__ od, __half* __restrict__ ot,
                           __half* __restrict__ oq, __half* __restrict__ oo)
{
    long idx = (long)blockIdx.x * blockDim.x + threadIdx.x;
    const float4* in; __half* out; long lidx;
    if (idx < 131072)       { in = wd; out = od; lidx = idx; }
    else if (idx < 196608)  { in = wt; out = ot; lidx = idx - 131072; }
    else if (idx < 393216)  { in = wq; out = oq; lidx = idx - 196608; }
    else if (idx < 458752)  { in = wo; out = oo; lidx = idx - 393216; }
    else return;
    float4 v = in[lidx];
    *(uint2*)(out + lidx * 4) =
        make_uint2(pk2h(__float2half_rn(v.x), __float2half_rn(v.y)),
                   pk2h(__float2half_rn(v.z), __float2half_rn(v.w)));
}

// ---------------------------------------------------------------------------
// GEMM: C[M,N] = A[M,K2] @ Wview[N,K2]^T + bias (+extra, MODE 1)
// A = [hi|lo] straight (strideA = K2).  W stored [N,Kb], viewed as [W|W]:
// B k-segment wraps at bWrap = Kb/64 iterations.
// Block 128x128, BK=64, 3-stage cp.async, 8 warps (2m x 4n), warp 64x32.
// MODE 0: fp32 out [*,N].  MODE 1: [hi|lo] fp16 out, row stride 1024.
// ---------------------------------------------------------------------------
#define STAGES      3
#define STAGE_BYTES 32768    // A 16KB + B 16KB

template <int MODE>
__global__ __launch_bounds__(256, 2)
void gemm_mma(const __half* __restrict__ A, const __half* __restrict__ B,
              const float* __restrict__ bias, const float* __restrict__ extra,
              void* __restrict__ Cout, int N, int K2, int Kb)
{
    extern __shared__ char sm[];
    const uint32_t smemBase = smem_u32(sm);
    const int tid    = threadIdx.x;
    const int lane   = tid & 31;
    const int wid    = tid >> 5;
    const int warp_m = wid >> 2;
    const int warp_n = wid & 3;
    const int mB     = blockIdx.y * 128;
    const int nB     = blockIdx.x * 128;
    const int bWrap  = Kb >> 6;

    // cp.async: 2048 16B chunks/stage (A 1024 + B 1024), 8 per thread
    uint32_t dstOff[8];
    const __half* gsrc[8];
#pragma unroll
    for (int j = 0; j < 8; j++) {
        int chunk = tid + 256 * j;
        int isB   = chunk >> 10;
        int cc    = chunk & 1023;
        int row   = cc >> 3, c = cc & 7;
        dstOff[j] = isB * 16384 + row * 128 + ((c ^ (row & 7)) << 4);
        gsrc[j] = (isB ? B + (size_t)(nB + row) * Kb
                       : A + (size_t)(mB + row) * K2) + c * 8;
    }

    // ldmatrix bases (stage 0, k-chunk 0)
    const int la = lane & 15, ha = lane >> 4;
    uint32_t baseA[4];
#pragma unroll
    for (int mi = 0; mi < 4; mi++) {
        int row = warp_m * 64 + mi * 16 + la;
        baseA[mi] = smemBase + row * 128 + ((ha ^ (row & 7)) << 4);
    }
    const int lb = (lane & 7) + ((lane >> 4) << 3);
    const int hb = (lane >> 3) & 1;
    uint32_t baseB[2];
#pragma unroll
    for (int n2 = 0; n2 < 2; n2++) {
        int row = warp_n * 32 + n2 * 16 + lb;
        baseB[n2] = smemBase + 16384 + row * 128 + ((hb ^ (row & 7)) << 4);
    }

    float acc[4][4][4];
#pragma unroll
    for (int mi = 0; mi < 4; mi++)
#pragma unroll
        for (int ni = 0; ni < 4; ni++)
#pragma unroll
            for (int e = 0; e < 4; e++) acc[mi][ni][e] = 0.f;

    const int nIter = K2 >> 6;

    // prologue: 2 stages
#pragma unroll
    for (int s = 0; s < STAGES - 1; s++) {
        const int bo = (s >= bWrap ? s - bWrap : s) * 64;
#pragma unroll
        for (int j = 0; j < 8; j++)
            CP_ASYNC(smemBase + s * STAGE_BYTES + dstOff[j],
                     gsrc[j] + (j < 4 ? s * 64 : bo));
        CP_COMMIT();
    }

    int stage = 0;
    for (int it = 0; it < nIter; it++) {
        CP_WAIT(1);
        __syncthreads();

        if (it + STAGES - 1 < nIter) {
            const int pit = it + STAGES - 1;
            const int pstage = (stage + STAGES - 1 >= STAGES) ? stage - 1 : stage + 2;
            const int aoff = pit * 64;
            const int boff = (pit >= bWrap ? pit - bWrap : pit) * 64;
#pragma unroll
            for (int j = 0; j < 8; j++)
                CP_ASYNC(smemBase + pstage * STAGE_BYTES + dstOff[j],
                         gsrc[j] + (j < 4 ? aoff : boff));
        }
        CP_COMMIT();

        const uint32_t stOff = (uint32_t)stage * STAGE_BYTES;
#pragma unroll
        for (int kk = 0; kk < 4; kk++) {
            uint32_t a[4][4], b[2][4];
#pragma unroll
            for (int mi = 0; mi < 4; mi++)
                ldsm4(a[mi], (baseA[mi] + stOff) ^ (kk << 5));
#pragma unroll
            for (int n2 = 0; n2 < 2; n2++)
                ldsm4(b[n2], (baseB[n2] + stOff) ^ (kk << 5));
#pragma unroll
            for (int mi = 0; mi < 4; mi++)
#pragma unroll
                for (int ni = 0; ni < 4; ni++)
                    mma16816(acc[mi][ni], a[mi],
                             b[ni >> 1][(ni & 1) * 2], b[ni >> 1][(ni & 1) * 2 + 1]);
        }
        stage = (stage + 1 == STAGES) ? 0 : stage + 1;
    }

    // ---------------- epilogue ----------------
    const int mWarp = mB + warp_m * 64;
    const int nWarp = nB + warp_n * 32;
#pragma unroll
    for (int mi = 0; mi < 4; mi++) {
#pragma unroll
        for (int ni = 0; ni < 4; ni++) {
            const int row0 = mWarp + mi * 16 + (lane >> 2);
            const int col  = nWarp + ni * 8 + (lane & 3) * 2;
            const float b0 = __ldg(bias + col);
            const float b1 = __ldg(bias + col + 1);
            float v0 = acc[mi][ni][0] + b0, v1 = acc[mi][ni][1] + b1;
            float v2 = acc[mi][ni][2] + b0, v3 = acc[mi][ni][3] + b1;
            if (MODE == 1) {
                const float* e0 = extra + (size_t)(row0 >> 3) * OUT_CH + col;
                const float* e1 = extra + (size_t)((row0 + 8) >> 3) * OUT_CH + col;
                v0 += __ldg(e0); v1 += __ldg(e0 + 1);
                v2 += __ldg(e1); v3 += __ldg(e1 + 1);
            }
            if (MODE == 0) {
                float* c0 = (float*)Cout + (size_t)row0 * N + col;
                float* c1 = (float*)Cout + (size_t)(row0 + 8) * N + col;
                *(float2*)c0 = make_float2(v0, v1);
                *(float2*)c1 = make_float2(v2, v3);
            } else {
                __half h0, l0, h1, l1, h2, l2, h3, l3;
                split_h(v0, h0, l0); split_h(v1, h1, l1);
                split_h(v2, h2, l2); split_h(v3, h3, l3);
                __half* o0 = (__half*)Cout + (size_t)row0 * 1024 + col;
                __half* o1 = (__half*)Cout + (size_t)(row0 + 8) * 1024 + col;
                *(uint32_t*)(o0)       = pk2h(h0, h1);
                *(uint32_t*)(o0 + 512) = pk2h(l0, l1);
                *(uint32_t*)(o1)       = pk2h(h2, h3);
                *(uint32_t*)(o1 + 512) = pk2h(l2, l3);
            }
        }
    }
}

// ---------------------------------------------------------------------------
// Per-row attention (row-local 8x8 head softmax), writes [hi|lo] fp16.
// ---------------------------------------------------------------------------
__global__ __launch_bounds__(256)
void attn_kernel(const float* __restrict__ qkv, __half* __restrict__ out2)
{
    __shared__ __align__(16) float sq[4][512];
    __shared__ __align__(16) float sk[4][512];
    __shared__ __align__(16) float sv[4][8 * 68];
    __shared__ float sS[4][64];

    const int tid = threadIdx.x;
    const size_t rowBase = (size_t)blockIdx.x * 4;

    const float4* src = (const float4*)(qkv + rowBase * 1536);
#pragma unroll
    for (int i = 0; i < 6; i++) {
        int idx = tid + 256 * i;
        int r = idx / 384, f = idx - r * 384;
        float4 v = src[idx];
        if (f < 128)       ((float4*)sq[r])[f] = v;
        else if (f < 256)  ((float4*)sk[r])[f - 128] = v;
        else {
            int f2 = f - 256, kh = f2 >> 4, c4 = f2 & 15;
            *(float4*)&sv[r][kh * 68 + c4 * 4] = v;
        }
    }
    __syncthreads();

    const int r  = tid >> 6;
    const int j  = tid & 63;
    const int qh = j >> 3;
    const int kh = j & 7;

    const float4* q4 = (const float4*)&sq[r][qh * 64];
    float sc = 0.f;
#pragma unroll
    for (int i = 0; i < 16; i++) {
        int c4 = (kh + i) & 15;
        float4 a = q4[c4];
        float4 b = *(const float4*)&sk[r][kh * 64 + c4 * 4];
        sc += a.x * b.x + a.y * b.y + a.z * b.z + a.w * b.w;
    }
    sS[r][j] = sc * 0.125f;
    __syncthreads();

    if (j < 8) {
        float* w = &sS[r][j * 8];
        float mx = w[0];
#pragma unroll
        for (int i = 1; i < 8; i++) mx = fmaxf(mx, w[i]);
        float e[8]; float sum = 0.f;
#pragma unroll
        for (int i = 0; i < 8; i++) { e[i] = __expf(w[i] - mx); sum += e[i]; }
        float inv = 1.f / sum;
#pragma unroll
        for (int i = 0; i < 8; i++) w[i] = e[i] * inv;
    }
    __syncthreads();

    const int cb = (j & 7) * 8;
    float o[8];
#pragma unroll
    for (int i = 0; i < 8; i++) o[i] = 0.f;
#pragma unroll
    for (int kk = 0; kk < 8; kk++) {
        int kh2 = (kk + (j & 7)) & 7;
        float w = sS[r][qh * 8 + kh2];
        float4 v0 = *(const float4*)&sv[r][kh2 * 68 + cb];
        float4 v1 = *(const float4*)&sv[r][kh2 * 68 + cb + 4];
        o[0] += w * v0.x; o[1] += w * v0.y; o[2] += w * v0.z; o[3] += w * v0.w;
        o[4] += w * v1.x; o[5] += w * v1.y; o[6] += w * v1.z; o[7] += w * v1.w;
    }
    __half h[8], l[8];
#pragma unroll
    for (int i = 0; i < 8; i++) split_h(o[i], h[i], l[i]);
    uint4 hv = make_uint4(pk2h(h[0], h[1]), pk2h(h[2], h[3]),
                          pk2h(h[4], h[5]), pk2h(h[6], h[7]));
    uint4 lv = make_uint4(pk2h(l[0], l[1]), pk2h(l[2], l[3]),
                          pk2h(l[4], l[5]), pk2h(l[6], l[7]));
    __half* base = out2 + (rowBase + r) * 1024 + qh * 64 + cb;
    *(uint4*)(base)       = hv;
    *(uint4*)(base + 512) = lv;
}

// ---------------------------------------------------------------------------
extern "C" void kernel_launch(void* const* d_in, const int* in_sizes, int n_in,
                              void* d_out, int out_size)
{
    const float* x      = (const float*)d_in[0];
    const float* t      = (const float*)d_in[1];
    const float* W_down = (const float*)d_in[2];
    const float* b_down = (const float*)d_in[3];
    const float* W_t    = (const float*)d_in[4];
    const float* b_t    = (const float*)d_in[5];
    const float* W_qkv  = (const float*)d_in[6];
    const float* b_qkv  = (const float*)d_in[7];
    const float* W_out  = (const float*)d_in[8];
    const float* b_out  = (const float*)d_in[9];
    float* out = (float*)d_out;

    void* p;
    __half *t2, *x2a, *wd2, *wt2, *wq2, *wo2, *h2, *at2;
    float *temb, *qkv;
    cudaGetSymbolAddress(&p, g_t2);   t2  = (__half*)p;
    cudaGetSymbolAddress(&p, g_x2a);  x2a = (__half*)p;
    cudaGetSymbolAddress(&p, g_wd2);  wd2 = (__half*)p;
    cudaGetSymbolAddress(&p, g_wt2);  wt2 = (__half*)p;
    cudaGetSymbolAddress(&p, g_wq2);  wq2 = (__half*)p;
    cudaGetSymbolAddress(&p, g_wo2);  wo2 = (__half*)p;
    cudaGetSymbolAddress(&p, g_temb); temb = (float*)p;
    cudaGetSymbolAddress(&p, g_h2);   h2  = (__half*)p;
    cudaGetSymbolAddress(&p, g_qkv);  qkv = (float*)p;
    cudaGetSymbolAddress(&p, g_at2);  at2 = (__half*)p;

    const int dynSmem = STAGES * STAGE_BYTES;   // 96 KB
    cudaFuncSetAttribute(gemm_mma<0>, cudaFuncAttributeMaxDynamicSharedMemorySize, dynSmem);
    cudaFuncSetAttribute(gemm_mma<1>, cudaFuncAttributeMaxDynamicSharedMemorySize, dynSmem);

    // 0: weights  1: t split  2: x split
    conv_w_all<<<1792, 256>>>((const float4*)W_down, (const float4*)W_t,
                              (const float4*)W_qkv, (const float4*)W_out,
                              wd2, wt2, wq2, wo2);
    conv_act<<<(BSZ * T_DIM / 4 + 255) / 256, 256>>>((const float4*)t, t2,
                                                     T_DIM / 4, T_DIM,
                                                     (long)BSZ * T_DIM / 4);
    conv_act<<<((long)ROWS * IN_CH / 4 + 255) / 256, 256>>>((const float4*)x, x2a,
                                                            IN_CH / 4, IN_CH,
                                                            (long)ROWS * IN_CH / 4);

    // 3: temb = t @ W_t^T + b_t                       [8192, 512] fp32
    gemm_mma<0><<<dim3(4, 64), 256, dynSmem>>>(t2, wt2, b_t, nullptr, temb,
                                               OUT_CH, 2 * T_DIM, T_DIM);
    // 4: x2 = x @ W_down^T + b_down + temb -> [hi|lo] [65536, 1024 fp16]
    gemm_mma<1><<<dim3(4, 512), 256, dynSmem>>>(x2a, wd2, b_down, temb, h2,
                                                OUT_CH, 2 * IN_CH, IN_CH);
    // 5: qkv = x2 @ W_qkv^T + b_qkv                   [65536, 1536] fp32  (ncu)
    gemm_mma<0><<<dim3(12, 512), 256, dynSmem>>>(h2, wq2, b_qkv, nullptr, qkv,
                                                 3 * OUT_CH, 2 * OUT_CH, OUT_CH);
    // 6: attention -> [hi|lo]
    attn_kernel<<<ROWS / 4, 256>>>(qkv, at2);
    // 7: out = attn @ W_out^T + b_out                 [65536, 512] fp32
    gemm_mma<0><<<dim3(4, 512), 256, dynSmem>>>(at2, wo2, b_out, nullptr, out,
                                                OUT_CH, 2 * OUT_CH, OUT_CH);
}

// round 8
// speedup vs baseline: 11.3205x; 1.6215x over previous
#include <cuda_runtime.h>
#include <cuda_fp16.h>
#include <cstdint>
#include <cstddef>

// ---------------------------------------------------------------------------
// TSABlock, plain-fp16 mma.sync HMMA (tcgen05 blocked: harness PTX targets
// compute_103 without the 'a' feature set).
// All GEMMs: A fp16, W fp16, fp32 accumulate. Error budget measured R7:
// W-only fp16 rounding -> 3.4e-4 rel_err; adding A rounding -> ~4.8e-4
// predicted (threshold 1e-3).
// Attention is fully row-local (HEADS==CLIP==8 torch-.view quirk).
// ---------------------------------------------------------------------------

#define BSZ     8192
#define IN_CH   1024
#define OUT_CH  512
#define T_DIM   512
#define ROWS    65536

__device__ __half g_t16 [(size_t)BSZ  * T_DIM];
__device__ __half g_x16 [(size_t)ROWS * IN_CH];
__device__ __half g_wd2 [(size_t)OUT_CH * IN_CH];
__device__ __half g_wt2 [(size_t)OUT_CH * T_DIM];
__device__ __half g_wq2 [(size_t)3 * OUT_CH * OUT_CH];
__device__ __half g_wo2 [(size_t)OUT_CH * OUT_CH];
__device__ float  g_temb[(size_t)BSZ * OUT_CH];
__device__ __half g_h2  [(size_t)ROWS * OUT_CH];
__device__ __half g_qkv [(size_t)ROWS * 3 * OUT_CH];
__device__ __half g_at2 [(size_t)ROWS * OUT_CH];

// ---------------------------- helpers --------------------------------------
__device__ __forceinline__ uint32_t smem_u32(const void* p) {
    uint32_t a;
    asm("{ .reg .u64 t; cvta.to.shared.u64 t, %1; cvt.u32.u64 %0, t; }"
        : "=r"(a) : "l"(p));
    return a;
}
__device__ __forceinline__ void ldsm4(uint32_t* r, uint32_t addr) {
    asm volatile("ldmatrix.sync.aligned.m8n8.x4.shared.b16 {%0,%1,%2,%3}, [%4];"
                 : "=r"(r[0]), "=r"(r[1]), "=r"(r[2]), "=r"(r[3]) : "r"(addr));
}
__device__ __forceinline__ void mma16816(float* d, const uint32_t* a,
                                         uint32_t b0, uint32_t b1) {
    asm volatile("mma.sync.aligned.m16n8k16.row.col.f32.f16.f16.f32 "
                 "{%0,%1,%2,%3}, {%4,%5,%6,%7}, {%8,%9}, {%0,%1,%2,%3};"
                 : "+f"(d[0]), "+f"(d[1]), "+f"(d[2]), "+f"(d[3])
                 : "r"(a[0]), "r"(a[1]), "r"(a[2]), "r"(a[3]), "r"(b0), "r"(b1));
}
#define CP_ASYNC(dst, src) \
    asm volatile("cp.async.cg.shared.global [%0], [%1], 16;" :: "r"(dst), "l"(src))
#define CP_COMMIT() asm volatile("cp.async.commit_group;" ::: "memory")
#define CP_WAIT(n)  asm volatile("cp.async.wait_group %0;" :: "n"(n) : "memory")

__device__ __forceinline__ uint32_t pk2h(__half a, __half b) {
    return (uint32_t)__half_as_ushort(a) | ((uint32_t)__half_as_ushort(b) << 16);
}

// ---------------------------------------------------------------------------
// conv_f2h: plain fp32 -> fp16 elementwise (float4 granular)
// ---------------------------------------------------------------------------
__global__ void conv_f2h(const float4* __restrict__ in, __half* __restrict__ out,
                         long total4)
{
    long idx = (long)blockIdx.x * blockDim.x + threadIdx.x;
    if (idx >= total4) return;
    float4 v = in[idx];
    *(uint2*)(out + idx * 4) =
        make_uint2(pk2h(__float2half_rn(v.x), __float2half_rn(v.y)),
                   pk2h(__float2half_rn(v.z), __float2half_rn(v.w)));
}

// ---------------------------------------------------------------------------
// conv_w_all: 4 weight tensors fp32 -> fp16, one launch.
// float4 regions: W_down 131072 | W_t 65536 | W_qkv 196608 | W_out 65536
// ---------------------------------------------------------------------------
__global__ void conv_w_all(const float4* __restrict__ wd, const float4* __restrict__ wt,
                           const float4* __restrict__ wq, const float4* __restrict__ wo,
                           __half* __restrict__ od, __half* __restrict__ ot,
                           __half* __restrict__ oq, __half* __restrict__ oo)
{
    long idx = (long)blockIdx.x * blockDim.x + threadIdx.x;
    const float4* in; __half* out; long lidx;
    if (idx < 131072)       { in = wd; out = od; lidx = idx; }
    else if (idx < 196608)  { in = wt; out = ot; lidx = idx - 131072; }
    else if (idx < 393216)  { in = wq; out = oq; lidx = idx - 196608; }
    else if (idx < 458752)  { in = wo; out = oo; lidx = idx - 393216; }
    else return;
    float4 v = in[lidx];
    *(uint2*)(out + lidx * 4) =
        make_uint2(pk2h(__float2half_rn(v.x), __float2half_rn(v.y)),
                   pk2h(__float2half_rn(v.z), __float2half_rn(v.w)));
}

// ---------------------------------------------------------------------------
// GEMM: C[M,N] = A[M,K] @ W[N,K]^T + bias (+extra for MODE 1)
// Block 128x128, BK=64, 3-stage cp.async, 8 warps (2m x 4n), warp 64x32.
// MODE 0: fp32 out, row stride N.
// MODE 1: fp16 out, row stride 512, adds extra[m>>3, col] (temb).
// MODE 2: fp16 out, row stride N.
// ---------------------------------------------------------------------------
#define STAGES      3
#define STAGE_BYTES 32768    // A 16KB + B 16KB

template <int MODE>
__global__ __launch_bounds__(256, 2)
void gemm_mma(const __half* __restrict__ A, const __half* __restrict__ B,
              const float* __restrict__ bias, const float* __restrict__ extra,
              void* __restrict__ Cout, int N, int K)
{
    extern __shared__ char sm[];
    const uint32_t smemBase = smem_u32(sm);
    const int tid    = threadIdx.x;
    const int lane   = tid & 31;
    const int wid    = tid >> 5;
    const int warp_m = wid >> 2;
    const int warp_n = wid & 3;
    const int mB     = blockIdx.y * 128;
    const int nB     = blockIdx.x * 128;

    // cp.async: 2048 16B chunks/stage (A 1024 + B 1024), 8 per thread
    uint32_t dstOff[8];
    const __half* gsrc[8];
#pragma unroll
    for (int j = 0; j < 8; j++) {
        int chunk = tid + 256 * j;
        int isB   = chunk >> 10;
        int cc    = chunk & 1023;
        int row   = cc >> 3, c = cc & 7;
        dstOff[j] = isB * 16384 + row * 128 + ((c ^ (row & 7)) << 4);
        gsrc[j] = (isB ? B + (size_t)(nB + row) * K
                       : A + (size_t)(mB + row) * K) + c * 8;
    }

    // ldmatrix bases (stage 0, k-chunk 0)
    const int la = lane & 15, ha = lane >> 4;
    uint32_t baseA[4];
#pragma unroll
    for (int mi = 0; mi < 4; mi++) {
        int row = warp_m * 64 + mi * 16 + la;
        baseA[mi] = smemBase + row * 128 + ((ha ^ (row & 7)) << 4);
    }
    const int lb = (lane & 7) + ((lane >> 4) << 3);
    const int hb = (lane >> 3) & 1;
    uint32_t baseB[2];
#pragma unroll
    for (int n2 = 0; n2 < 2; n2++) {
        int row = warp_n * 32 + n2 * 16 + lb;
        baseB[n2] = smemBase + 16384 + row * 128 + ((hb ^ (row & 7)) << 4);
    }

    float acc[4][4][4];
#pragma unroll
    for (int mi = 0; mi < 4; mi++)
#pragma unroll
        for (int ni = 0; ni < 4; ni++)
#pragma unroll
            for (int e = 0; e < 4; e++) acc[mi][ni][e] = 0.f;

    const int nIter = K >> 6;

    // prologue: 2 stages
#pragma unroll
    for (int s = 0; s < STAGES - 1; s++) {
#pragma unroll
        for (int j = 0; j < 8; j++)
            CP_ASYNC(smemBase + s * STAGE_BYTES + dstOff[j], gsrc[j] + s * 64);
        CP_COMMIT();
    }

    int stage = 0;
    for (int it = 0; it < nIter; it++) {
        CP_WAIT(1);
        __syncthreads();

        if (it + STAGES - 1 < nIter) {
            const int pit = it + STAGES - 1;
            const int pstage = (stage + STAGES - 1 >= STAGES) ? stage - 1 : stage + 2;
            const int off = pit * 64;
#pragma unroll
            for (int j = 0; j < 8; j++)
                CP_ASYNC(smemBase + pstage * STAGE_BYTES + dstOff[j], gsrc[j] + off);
        }
        CP_COMMIT();

        const uint32_t stOff = (uint32_t)stage * STAGE_BYTES;
#pragma unroll
        for (int kk = 0; kk < 4; kk++) {
            uint32_t a[4][4], b[2][4];
#pragma unroll
            for (int mi = 0; mi < 4; mi++)
                ldsm4(a[mi], (baseA[mi] + stOff) ^ (kk << 5));
#pragma unroll
            for (int n2 = 0; n2 < 2; n2++)
                ldsm4(b[n2], (baseB[n2] + stOff) ^ (kk << 5));
#pragma unroll
            for (int mi = 0; mi < 4; mi++)
#pragma unroll
                for (int ni = 0; ni < 4; ni++)
                    mma16816(acc[mi][ni], a[mi],
                             b[ni >> 1][(ni & 1) * 2], b[ni >> 1][(ni & 1) * 2 + 1]);
        }
        stage = (stage + 1 == STAGES) ? 0 : stage + 1;
    }

    // ---------------- epilogue ----------------
    const int mWarp = mB + warp_m * 64;
    const int nWarp = nB + warp_n * 32;
#pragma unroll
    for (int mi = 0; mi < 4; mi++) {
#pragma unroll
        for (int ni = 0; ni < 4; ni++) {
            const int row0 = mWarp + mi * 16 + (lane >> 2);
            const int col  = nWarp + ni * 8 + (lane & 3) * 2;
            const float b0 = __ldg(bias + col);
            const float b1 = __ldg(bias + col + 1);
            float v0 = acc[mi][ni][0] + b0, v1 = acc[mi][ni][1] + b1;
            float v2 = acc[mi][ni][2] + b0, v3 = acc[mi][ni][3] + b1;
            if (MODE == 1) {
                const float* e0 = extra + (size_t)(row0 >> 3) * OUT_CH + col;
                const float* e1 = extra + (size_t)((row0 + 8) >> 3) * OUT_CH + col;
                v0 += __ldg(e0); v1 += __ldg(e0 + 1);
                v2 += __ldg(e1); v3 += __ldg(e1 + 1);
            }
            if (MODE == 0) {
                float* c0 = (float*)Cout + (size_t)row0 * N + col;
                float* c1 = (float*)Cout + (size_t)(row0 + 8) * N + col;
                *(float2*)c0 = make_float2(v0, v1);
                *(float2*)c1 = make_float2(v2, v3);
            } else {
                const int stride = (MODE == 1) ? OUT_CH : N;
                __half* o0 = (__half*)Cout + (size_t)row0 * stride + col;
                __half* o1 = (__half*)Cout + (size_t)(row0 + 8) * stride + col;
                *(uint32_t*)o0 = pk2h(__float2half_rn(v0), __float2half_rn(v1));
                *(uint32_t*)o1 = pk2h(__float2half_rn(v2), __float2half_rn(v3));
            }
        }
    }
}

// ---------------------------------------------------------------------------
// Per-row attention (row-local 8x8 head softmax), fp16 in -> fp16 out.
// ---------------------------------------------------------------------------
__global__ __launch_bounds__(256)
void attn_kernel(const __half* __restrict__ qkv, __half* __restrict__ out2)
{
    __shared__ __align__(16) float sq[4][512];
    __shared__ __align__(16) float sk[4][512];
    __shared__ __align__(16) float sv[4][8 * 68];
    __shared__ float sS[4][64];

    const int tid = threadIdx.x;
    const size_t rowBase = (size_t)blockIdx.x * 4;

    // cooperative load: 4 rows x 1536 halfs = 768 uint4, 3 per thread
    const uint4* src = (const uint4*)(qkv + rowBase * 1536);
#pragma unroll
    for (int i = 0; i < 3; i++) {
        int idx = tid + 256 * i;            // 0..767
        int r = idx / 192, f = idx - r * 192;
        uint4 u = src[idx];
        const __half2* hp = (const __half2*)&u;
        float vals[8];
#pragma unroll
        for (int q = 0; q < 4; q++) {
            float2 fp = __half22float2(hp[q]);
            vals[2 * q] = fp.x; vals[2 * q + 1] = fp.y;
        }
        int c = f * 8;                      // position within 1536
        float4 lo = make_float4(vals[0], vals[1], vals[2], vals[3]);
        float4 hi = make_float4(vals[4], vals[5], vals[6], vals[7]);
        if (c < 512) {
            *(float4*)&sq[r][c] = lo;
            *(float4*)&sq[r][c + 4] = hi;
        } else if (c < 1024) {
            *(float4*)&sk[r][c - 512] = lo;
            *(float4*)&sk[r][c - 508] = hi;
        } else {
            int cc = c - 1024, kh = cc >> 6, cb2 = cc & 63;
            *(float4*)&sv[r][kh * 68 + cb2] = lo;
            *(float4*)&sv[r][kh * 68 + cb2 + 4] = hi;
        }
    }
    __syncthreads();

    const int r  = tid >> 6;
    const int j  = tid & 63;
    const int qh = j >> 3;
    const int kh = j & 7;

    const float4* q4 = (const float4*)&sq[r][qh * 64];
    float sc = 0.f;
#pragma unroll
    for (int i = 0; i < 16; i++) {
        int c4 = (kh + i) & 15;
        float4 a = q4[c4];
        float4 b = *(const float4*)&sk[r][kh * 64 + c4 * 4];
        sc += a.x * b.x + a.y * b.y + a.z * b.z + a.w * b.w;
    }
    sS[r][j] = sc * 0.125f;
    __syncthreads();

    if (j < 8) {
        float* w = &sS[r][j * 8];
        float mx = w[0];
#pragma unroll
        for (int i = 1; i < 8; i++) mx = fmaxf(mx, w[i]);
        float e[8]; float sum = 0.f;
#pragma unroll
        for (int i = 0; i < 8; i++) { e[i] = __expf(w[i] - mx); sum += e[i]; }
        float inv = 1.f / sum;
#pragma unroll
        for (int i = 0; i < 8; i++) w[i] = e[i] * inv;
    }
    __syncthreads();

    const int cb = (j & 7) * 8;
    float o[8];
#pragma unroll
    for (int i = 0; i < 8; i++) o[i] = 0.f;
#pragma unroll
    for (int kk = 0; kk < 8; kk++) {
        int kh2 = (kk + (j & 7)) & 7;
        float w = sS[r][qh * 8 + kh2];
        float4 v0 = *(const float4*)&sv[r][kh2 * 68 + cb];
        float4 v1 = *(const float4*)&sv[r][kh2 * 68 + cb + 4];
        o[0] += w * v0.x; o[1] += w * v0.y; o[2] += w * v0.z; o[3] += w * v0.w;
        o[4] += w * v1.x; o[5] += w * v1.y; o[6] += w * v1.z; o[7] += w * v1.w;
    }
    uint4 hv = make_uint4(
        pk2h(__float2half_rn(o[0]), __float2half_rn(o[1])),
        pk2h(__float2half_rn(o[2]), __float2half_rn(o[3])),
        pk2h(__float2half_rn(o[4]), __float2half_rn(o[5])),
        pk2h(__float2half_rn(o[6]), __float2half_rn(o[7])));
    __half* base = out2 + (rowBase + r) * 512 + qh * 64 + cb;
    *(uint4*)base = hv;
}

// ---------------------------------------------------------------------------
extern "C" void kernel_launch(void* const* d_in, const int* in_sizes, int n_in,
                              void* d_out, int out_size)
{
    const float* x      = (const float*)d_in[0];
    const float* t      = (const float*)d_in[1];
    const float* W_down = (const float*)d_in[2];
    const float* b_down = (const float*)d_in[3];
    const float* W_t    = (const float*)d_in[4];
    const float* b_t    = (const float*)d_in[5];
    const float* W_qkv  = (const float*)d_in[6];
    const float* b_qkv  = (const float*)d_in[7];
    const float* W_out  = (const float*)d_in[8];
    const float* b_out  = (const float*)d_in[9];
    float* out = (float*)d_out;

    void* p;
    __half *t16, *x16, *wd2, *wt2, *wq2, *wo2, *h2, *qkv, *at2;
    float *temb;
    cudaGetSymbolAddress(&p, g_t16);  t16 = (__half*)p;
    cudaGetSymbolAddress(&p, g_x16);  x16 = (__half*)p;
    cudaGetSymbolAddress(&p, g_wd2);  wd2 = (__half*)p;
    cudaGetSymbolAddress(&p, g_wt2);  wt2 = (__half*)p;
    cudaGetSymbolAddress(&p, g_wq2);  wq2 = (__half*)p;
    cudaGetSymbolAddress(&p, g_wo2);  wo2 = (__half*)p;
    cudaGetSymbolAddress(&p, g_temb); temb = (float*)p;
    cudaGetSymbolAddress(&p, g_h2);   h2  = (__half*)p;
    cudaGetSymbolAddress(&p, g_qkv);  qkv = (__half*)p;
    cudaGetSymbolAddress(&p, g_at2);  at2 = (__half*)p;

    const int dynSmem = STAGES * STAGE_BYTES;   // 96 KB
    cudaFuncSetAttribute(gemm_mma<0>, cudaFuncAttributeMaxDynamicSharedMemorySize, dynSmem);
    cudaFuncSetAttribute(gemm_mma<1>, cudaFuncAttributeMaxDynamicSharedMemorySize, dynSmem);
    cudaFuncSetAttribute(gemm_mma<2>, cudaFuncAttributeMaxDynamicSharedMemorySize, dynSmem);

    const long t_total4 = (long)BSZ * T_DIM / 4;     // 1,048,576
    const long x_total4 = (long)ROWS * IN_CH / 4;    // 16,777,216

    // 0: weights   1: t    2: x
    conv_w_all<<<1792, 256>>>((const float4*)W_down, (const float4*)W_t,
                              (const float4*)W_qkv, (const float4*)W_out,
                              wd2, wt2, wq2, wo2);
    conv_f2h<<<(int)((t_total4 + 255) / 256), 256>>>((const float4*)t, t16, t_total4);
    conv_f2h<<<(int)((x_total4 + 255) / 256), 256>>>((const float4*)x, x16, x_total4);

    // 3: temb = t @ W_t^T + b_t                       [8192, 512] fp32
    gemm_mma<0><<<dim3(4, 64), 256, dynSmem>>>(t16, wt2, b_t, nullptr, temb,
                                               OUT_CH, T_DIM);
    // 4: x2 = x @ W_down^T + b_down + temb -> fp16    [65536, 512]
    gemm_mma<1><<<dim3(4, 512), 256, dynSmem>>>(x16, wd2, b_down, temb, h2,
                                                OUT_CH, IN_CH);
    // 5: qkv = x2 @ W_qkv^T + b_qkv -> fp16           [65536, 1536]  (ncu)
    gemm_mma<2><<<dim3(12, 512), 256, dynSmem>>>(h2, wq2, b_qkv, nullptr, qkv,
                                                 3 * OUT_CH, OUT_CH);
    // 6: attention -> fp16                            [65536, 512]
    attn_kernel<<<ROWS / 4, 256>>>(qkv, at2);
    // 7: out = attn @ W_out^T + b_out                 [65536, 512] fp32
    gemm_mma<0><<<dim3(4, 512), 256, dynSmem>>>(at2, wo2, b_out, nullptr, out,
                                                OUT_CH, OUT_CH);
}

// round 10
// speedup vs baseline: 12.0249x; 1.0622x over previous
#include <cuda_runtime.h>
#include <cuda_fp16.h>
#include <cstdint>
#include <cstddef>

// ---------------------------------------------------------------------------
// TSABlock, plain-fp16 mma.sync HMMA (tcgen05 blocked: harness PTX targets
// compute_103 without the 'a' feature set).
// GEMMs: A fp16, W fp16, fp32 accumulate (calibrated rel_err ~5.2e-4).
// Attention is fully row-local (HEADS==CLIP==8 torch-.view quirk); v2:
// raw half2 smem, shuffle softmax, single barrier.  R10 fix: full 768-uint4
// cooperative copy (R9 copied only half the tile -> garbage V).
// ---------------------------------------------------------------------------

#define BSZ     8192
#define IN_CH   1024
#define OUT_CH  512
#define T_DIM   512
#define ROWS    65536

__device__ __half g_t16 [(size_t)BSZ  * T_DIM];
__device__ __half g_x16 [(size_t)ROWS * IN_CH];
__device__ __half g_wd2 [(size_t)OUT_CH * IN_CH];
__device__ __half g_wt2 [(size_t)OUT_CH * T_DIM];
__device__ __half g_wq2 [(size_t)3 * OUT_CH * OUT_CH];
__device__ __half g_wo2 [(size_t)OUT_CH * OUT_CH];
__device__ float  g_temb[(size_t)BSZ * OUT_CH];
__device__ __half g_h2  [(size_t)ROWS * OUT_CH];
__device__ __half g_qkv [(size_t)ROWS * 3 * OUT_CH];
__device__ __half g_at2 [(size_t)ROWS * OUT_CH];

// ---------------------------- helpers --------------------------------------
__device__ __forceinline__ uint32_t smem_u32(const void* p) {
    uint32_t a;
    asm("{ .reg .u64 t; cvta.to.shared.u64 t, %1; cvt.u32.u64 %0, t; }"
        : "=r"(a) : "l"(p));
    return a;
}
__device__ __forceinline__ void ldsm4(uint32_t* r, uint32_t addr) {
    asm volatile("ldmatrix.sync.aligned.m8n8.x4.shared.b16 {%0,%1,%2,%3}, [%4];"
                 : "=r"(r[0]), "=r"(r[1]), "=r"(r[2]), "=r"(r[3]) : "r"(addr));
}
__device__ __forceinline__ void mma16816(float* d, const uint32_t* a,
                                         uint32_t b0, uint32_t b1) {
    asm volatile("mma.sync.aligned.m16n8k16.row.col.f32.f16.f16.f32 "
                 "{%0,%1,%2,%3}, {%4,%5,%6,%7}, {%8,%9}, {%0,%1,%2,%3};"
                 : "+f"(d[0]), "+f"(d[1]), "+f"(d[2]), "+f"(d[3])
                 : "r"(a[0]), "r"(a[1]), "r"(a[2]), "r"(a[3]), "r"(b0), "r"(b1));
}
#define CP_ASYNC(dst, src) \
    asm volatile("cp.async.cg.shared.global [%0], [%1], 16;" :: "r"(dst), "l"(src))
#define CP_COMMIT() asm volatile("cp.async.commit_group;" ::: "memory")
#define CP_WAIT(n)  asm volatile("cp.async.wait_group %0;" :: "n"(n) : "memory")

__device__ __forceinline__ uint32_t pk2h(__half a, __half b) {
    return (uint32_t)__half_as_ushort(a) | ((uint32_t)__half_as_ushort(b) << 16);
}

// ---------------------------------------------------------------------------
// conv_f2h: plain fp32 -> fp16 elementwise (float4 granular)
// ---------------------------------------------------------------------------
__global__ void conv_f2h(const float4* __restrict__ in, __half* __restrict__ out,
                         long total4)
{
    long idx = (long)blockIdx.x * blockDim.x + threadIdx.x;
    if (idx >= total4) return;
    float4 v = in[idx];
    *(uint2*)(out + idx * 4) =
        make_uint2(pk2h(__float2half_rn(v.x), __float2half_rn(v.y)),
                   pk2h(__float2half_rn(v.z), __float2half_rn(v.w)));
}

// ---------------------------------------------------------------------------
// conv_w_all: 4 weight tensors fp32 -> fp16, one launch.
// float4 regions: W_down 131072 | W_t 65536 | W_qkv 196608 | W_out 65536
// ---------------------------------------------------------------------------
__global__ void conv_w_all(const float4* __restrict__ wd, const float4* __restrict__ wt,
                           const float4* __restrict__ wq, const float4* __restrict__ wo,
                           __half* __restrict__ od, __half* __restrict__ ot,
                           __half* __restrict__ oq, __half* __restrict__ oo)
{
    long idx = (long)blockIdx.x * blockDim.x + threadIdx.x;
    const float4* in; __half* out; long lidx;
    if (idx < 131072)       { in = wd; out = od; lidx = idx; }
    else if (idx < 196608)  { in = wt; out = ot; lidx = idx - 131072; }
    else if (idx < 393216)  { in = wq; out = oq; lidx = idx - 196608; }
    else if (idx < 458752)  { in = wo; out = oo; lidx = idx - 393216; }
    else return;
    float4 v = in[lidx];
    *(uint2*)(out + lidx * 4) =
        make_uint2(pk2h(__float2half_rn(v.x), __float2half_rn(v.y)),
                   pk2h(__float2half_rn(v.z), __float2half_rn(v.w)));
}

// ---------------------------------------------------------------------------
// GEMM: C[M,N] = A[M,K] @ W[N,K]^T + bias (+extra for MODE 1)
// Block 128x128, BK=64, 3-stage cp.async, 8 warps (2m x 4n), warp 64x32.
// MODE 0: fp32 out, row stride N.
// MODE 1: fp16 out, row stride 512, adds extra[m>>3, col] (temb).
// MODE 2: fp16 out, row stride N.
// ---------------------------------------------------------------------------
#define STAGES      3
#define STAGE_BYTES 32768    // A 16KB + B 16KB

template <int MODE>
__global__ __launch_bounds__(256, 2)
void gemm_mma(const __half* __restrict__ A, const __half* __restrict__ B,
              const float* __restrict__ bias, const float* __restrict__ extra,
              void* __restrict__ Cout, int N, int K)
{
    extern __shared__ char sm[];
    const uint32_t smemBase = smem_u32(sm);
    const int tid    = threadIdx.x;
    const int lane   = tid & 31;
    const int wid    = tid >> 5;
    const int warp_m = wid >> 2;
    const int warp_n = wid & 3;
    const int mB     = blockIdx.y * 128;
    const int nB     = blockIdx.x * 128;

    // cp.async: 2048 16B chunks/stage (A 1024 + B 1024), 8 per thread
    uint32_t dstOff[8];
    const __half* gsrc[8];
#pragma unroll
    for (int j = 0; j < 8; j++) {
        int chunk = tid + 256 * j;
        int isB   = chunk >> 10;
        int cc    = chunk & 1023;
        int row   = cc >> 3, c = cc & 7;
        dstOff[j] = isB * 16384 + row * 128 + ((c ^ (row & 7)) << 4);
        gsrc[j] = (isB ? B + (size_t)(nB + row) * K
                       : A + (size_t)(mB + row) * K) + c * 8;
    }

    // ldmatrix bases (stage 0, k-chunk 0)
    const int la = lane & 15, ha = lane >> 4;
    uint32_t baseA[4];
#pragma unroll
    for (int mi = 0; mi < 4; mi++) {
        int row = warp_m * 64 + mi * 16 + la;
        baseA[mi] = smemBase + row * 128 + ((ha ^ (row & 7)) << 4);
    }
    const int lb = (lane & 7) + ((lane >> 4) << 3);
    const int hb = (lane >> 3) & 1;
    uint32_t baseB[2];
#pragma unroll
    for (int n2 = 0; n2 < 2; n2++) {
        int row = warp_n * 32 + n2 * 16 + lb;
        baseB[n2] = smemBase + 16384 + row * 128 + ((hb ^ (row & 7)) << 4);
    }

    float acc[4][4][4];
#pragma unroll
    for (int mi = 0; mi < 4; mi++)
#pragma unroll
        for (int ni = 0; ni < 4; ni++)
#pragma unroll
            for (int e = 0; e < 4; e++) acc[mi][ni][e] = 0.f;

    const int nIter = K >> 6;

    // prologue: 2 stages
#pragma unroll
    for (int s = 0; s < STAGES - 1; s++) {
#pragma unroll
        for (int j = 0; j < 8; j++)
            CP_ASYNC(smemBase + s * STAGE_BYTES + dstOff[j], gsrc[j] + s * 64);
        CP_COMMIT();
    }

    int stage = 0;
    for (int it = 0; it < nIter; it++) {
        CP_WAIT(1);
        __syncthreads();

        if (it + STAGES - 1 < nIter) {
            const int pit = it + STAGES - 1;
            const int pstage = (stage + STAGES - 1 >= STAGES) ? stage - 1 : stage + 2;
            const int off = pit * 64;
#pragma unroll
            for (int j = 0; j < 8; j++)
                CP_ASYNC(smemBase + pstage * STAGE_BYTES + dstOff[j], gsrc[j] + off);
        }
        CP_COMMIT();

        const uint32_t stOff = (uint32_t)stage * STAGE_BYTES;
#pragma unroll
        for (int kk = 0; kk < 4; kk++) {
            uint32_t a[4][4], b[2][4];
#pragma unroll
            for (int mi = 0; mi < 4; mi++)
                ldsm4(a[mi], (baseA[mi] + stOff) ^ (kk << 5));
#pragma unroll
            for (int n2 = 0; n2 < 2; n2++)
                ldsm4(b[n2], (baseB[n2] + stOff) ^ (kk << 5));
#pragma unroll
            for (int mi = 0; mi < 4; mi++)
#pragma unroll
                for (int ni = 0; ni < 4; ni++)
                    mma16816(acc[mi][ni], a[mi],
                             b[ni >> 1][(ni & 1) * 2], b[ni >> 1][(ni & 1) * 2 + 1]);
        }
        stage = (stage + 1 == STAGES) ? 0 : stage + 1;
    }

    // ---------------- epilogue ----------------
    const int mWarp = mB + warp_m * 64;
    const int nWarp = nB + warp_n * 32;
#pragma unroll
    for (int mi = 0; mi < 4; mi++) {
#pragma unroll
        for (int ni = 0; ni < 4; ni++) {
            const int row0 = mWarp + mi * 16 + (lane >> 2);
            const int col  = nWarp + ni * 8 + (lane & 3) * 2;
            const float b0 = __ldg(bias + col);
            const float b1 = __ldg(bias + col + 1);
            float v0 = acc[mi][ni][0] + b0, v1 = acc[mi][ni][1] + b1;
            float v2 = acc[mi][ni][2] + b0, v3 = acc[mi][ni][3] + b1;
            if (MODE == 1) {
                const float* e0 = extra + (size_t)(row0 >> 3) * OUT_CH + col;
                const float* e1 = extra + (size_t)((row0 + 8) >> 3) * OUT_CH + col;
                v0 += __ldg(e0); v1 += __ldg(e0 + 1);
                v2 += __ldg(e1); v3 += __ldg(e1 + 1);
            }
            if (MODE == 0) {
                float* c0 = (float*)Cout + (size_t)row0 * N + col;
                float* c1 = (float*)Cout + (size_t)(row0 + 8) * N + col;
                *(float2*)c0 = make_float2(v0, v1);
                *(float2*)c1 = make_float2(v2, v3);
            } else {
                const int stride = (MODE == 1) ? OUT_CH : N;
                __half* o0 = (__half*)Cout + (size_t)row0 * stride + col;
                __half* o1 = (__half*)Cout + (size_t)(row0 + 8) * stride + col;
                *(uint32_t*)o0 = pk2h(__float2half_rn(v0), __float2half_rn(v1));
                *(uint32_t*)o1 = pk2h(__float2half_rn(v2), __float2half_rn(v3));
            }
        }
    }
}

// ---------------------------------------------------------------------------
// Per-row attention v2 (fixed): raw half2 smem, shuffle softmax, one barrier.
// Block = 256 threads = 4 rows x 64 (qh,kh) threads.
// Row layout in smem: [q 512 | k 512 | v 512] halfs (verbatim qkv row).
// ---------------------------------------------------------------------------
__global__ __launch_bounds__(256)
void attn_kernel(const __half* __restrict__ qkv, __half* __restrict__ out2)
{
    __shared__ __align__(16) __half s[4][1536];   // 12 KB

    const int tid = threadIdx.x;
    const size_t rowBase = (size_t)blockIdx.x * 4;

    // cooperative raw copy: 4 rows x 1536 halfs = 12288 B = 768 uint4,
    // 3 per thread (R9 bug: only 384 copied).
    const uint4* src = (const uint4*)(qkv + rowBase * 1536);
    uint4* dst = (uint4*)&s[0][0];
    dst[tid]       = src[tid];
    dst[256 + tid] = src[256 + tid];
    dst[512 + tid] = src[512 + tid];
    __syncthreads();

    const int r  = tid >> 6;
    const int j  = tid & 63;
    const int qh = j >> 3;
    const int kh = j & 7;       // also the output chunk selector

    const __half* q = &s[r][0];
    const __half* k = &s[r][512];
    const __half* v = &s[r][1024];

    // ---- score: dot(q[qh], k[kh]) over 64 ch, 8 chunks of 8 halfs ----
    float sc = 0.f;
#pragma unroll
    for (int c = 0; c < 8; c++) {
        const int cc = (kh + c) & 7;                    // bank rotation
        uint4 qu = *(const uint4*)(q + qh * 64 + cc * 8);
        uint4 ku = *(const uint4*)(k + kh * 64 + cc * 8);
        const __half2* qp = (const __half2*)&qu;
        const __half2* kp = (const __half2*)&ku;
#pragma unroll
        for (int e = 0; e < 4; e++) {
            float2 a = __half22float2(qp[e]);
            float2 b = __half22float2(kp[e]);
            sc += a.x * b.x + a.y * b.y;
        }
    }
    sc *= 0.125f;   // (ch^-1/4)^2 = 1/8

    // ---- softmax over kh within each 8-lane group (shuffle butterflies) ----
    float mx = sc;
#pragma unroll
    for (int d = 1; d < 8; d <<= 1)
        mx = fmaxf(mx, __shfl_xor_sync(0xffffffffu, mx, d, 8));
    float e = __expf(sc - mx);
    float sum = e;
#pragma unroll
    for (int d = 1; d < 8; d <<= 1)
        sum += __shfl_xor_sync(0xffffffffu, sum, d, 8);
    const float wOwn = e / sum;     // this thread's w[qh][kh]

    // ---- output: channels qh*64 + kh*8 .. +8 ----
    const int lane = tid & 31;
    const int gBase = lane & 24;    // lane group base (qh within warp)
    float o[8];
#pragma unroll
    for (int i = 0; i < 8; i++) o[i] = 0.f;
#pragma unroll
    for (int kk = 0; kk < 8; kk++) {
        const int kh2 = (kk + kh) & 7;                  // bank rotation
        const float wv = __shfl_sync(0xffffffffu, wOwn, gBase + kh2);
        uint4 vu = *(const uint4*)(v + kh2 * 64 + kh * 8);
        const __half2* vp = (const __half2*)&vu;
#pragma unroll
        for (int ee = 0; ee < 4; ee++) {
            float2 b = __half22float2(vp[ee]);
            o[2 * ee]     += wv * b.x;
            o[2 * ee + 1] += wv * b.y;
        }
    }

    uint4 hv = make_uint4(
        pk2h(__float2half_rn(o[0]), __float2half_rn(o[1])),
        pk2h(__float2half_rn(o[2]), __float2half_rn(o[3])),
        pk2h(__float2half_rn(o[4]), __float2half_rn(o[5])),
        pk2h(__float2half_rn(o[6]), __float2half_rn(o[7])));
    __half* base = out2 + (rowBase + r) * 512 + qh * 64 + kh * 8;
    *(uint4*)base = hv;
}

// ---------------------------------------------------------------------------
extern "C" void kernel_launch(void* const* d_in, const int* in_sizes, int n_in,
                              void* d_out, int out_size)
{
    const float* x      = (const float*)d_in[0];
    const float* t      = (const float*)d_in[1];
    const float* W_down = (const float*)d_in[2];
    const float* b_down = (const float*)d_in[3];
    const float* W_t    = (const float*)d_in[4];
    const float* b_t    = (const float*)d_in[5];
    const float* W_qkv  = (const float*)d_in[6];
    const float* b_qkv  = (const float*)d_in[7];
    const float* W_out  = (const float*)d_in[8];
    const float* b_out  = (const float*)d_in[9];
    float* out = (float*)d_out;

    void* p;
    __half *t16, *x16, *wd2, *wt2, *wq2, *wo2, *h2, *qkv, *at2;
    float *temb;
    cudaGetSymbolAddress(&p, g_t16);  t16 = (__half*)p;
    cudaGetSymbolAddress(&p, g_x16);  x16 = (__half*)p;
    cudaGetSymbolAddress(&p, g_wd2);  wd2 = (__half*)p;
    cudaGetSymbolAddress(&p, g_wt2);  wt2 = (__half*)p;
    cudaGetSymbolAddress(&p, g_wq2);  wq2 = (__half*)p;
    cudaGetSymbolAddress(&p, g_wo2);  wo2 = (__half*)p;
    cudaGetSymbolAddress(&p, g_temb); temb = (float*)p;
    cudaGetSymbolAddress(&p, g_h2);   h2  = (__half*)p;
    cudaGetSymbolAddress(&p, g_qkv);  qkv = (__half*)p;
    cudaGetSymbolAddress(&p, g_at2);  at2 = (__half*)p;

    const int dynSmem = STAGES * STAGE_BYTES;   // 96 KB
    cudaFuncSetAttribute(gemm_mma<0>, cudaFuncAttributeMaxDynamicSharedMemorySize, dynSmem);
    cudaFuncSetAttribute(gemm_mma<1>, cudaFuncAttributeMaxDynamicSharedMemorySize, dynSmem);
    cudaFuncSetAttribute(gemm_mma<2>, cudaFuncAttributeMaxDynamicSharedMemorySize, dynSmem);

    const long t_total4 = (long)BSZ * T_DIM / 4;     // 1,048,576
    const long x_total4 = (long)ROWS * IN_CH / 4;    // 16,777,216

    // 0: weights   1: t    2: x
    conv_w_all<<<1792, 256>>>((const float4*)W_down, (const float4*)W_t,
                              (const float4*)W_qkv, (const float4*)W_out,
                              wd2, wt2, wq2, wo2);
    conv_f2h<<<(int)((t_total4 + 255) / 256), 256>>>((const float4*)t, t16, t_total4);
    conv_f2h<<<(int)((x_total4 + 255) / 256), 256>>>((const float4*)x, x16, x_total4);

    // 3: temb = t @ W_t^T + b_t                       [8192, 512] fp32
    gemm_mma<0><<<dim3(4, 64), 256, dynSmem>>>(t16, wt2, b_t, nullptr, temb,
                                               OUT_CH, T_DIM);
    // 4: x2 = x @ W_down^T + b_down + temb -> fp16    [65536, 512]
    gemm_mma<1><<<dim3(4, 512), 256, dynSmem>>>(x16, wd2, b_down, temb, h2,
                                                OUT_CH, IN_CH);
    // 5: qkv = x2 @ W_qkv^T + b_qkv -> fp16           [65536, 1536]
    gemm_mma<2><<<dim3(12, 512), 256, dynSmem>>>(h2, wq2, b_qkv, nullptr, qkv,
                                                 3 * OUT_CH, OUT_CH);
    // 6: attention -> fp16                            [65536, 512]
    attn_kernel<<<ROWS / 4, 256>>>(qkv, at2);
    // 7: out = attn @ W_out^T + b_out                 [65536, 512] fp32
    gemm_mma<0><<<dim3(4, 512), 256, dynSmem>>>(at2, wo2, b_out, nullptr, out,
                                                OUT_CH, OUT_CH);
}

// round 11
// speedup vs baseline: 12.0832x; 1.0048x over previous
#include <cuda_runtime.h>
#include <cuda_fp16.h>
#include <cstdint>
#include <cstddef>

// ---------------------------------------------------------------------------
// TSABlock, plain-fp16 mma.sync HMMA (tcgen05 blocked: harness PTX targets
// compute_103 without the 'a' feature set).
// GEMMs: A fp16, W fp16, fp32 accumulate (calibrated rel_err ~5.2e-4).
// Attention fully row-local (HEADS==CLIP==8 torch-.view quirk): half2 smem,
// shuffle softmax, single barrier.
// R11: single fused conversion kernel (one wave), hoisted epilogue bias.
// ---------------------------------------------------------------------------

#define BSZ     8192
#define IN_CH   1024
#define OUT_CH  512
#define T_DIM   512
#define ROWS    65536

__device__ __half g_t16 [(size_t)BSZ  * T_DIM];
__device__ __half g_x16 [(size_t)ROWS * IN_CH];
__device__ __half g_wd2 [(size_t)OUT_CH * IN_CH];
__device__ __half g_wt2 [(size_t)OUT_CH * T_DIM];
__device__ __half g_wq2 [(size_t)3 * OUT_CH * OUT_CH];
__device__ __half g_wo2 [(size_t)OUT_CH * OUT_CH];
__device__ float  g_temb[(size_t)BSZ * OUT_CH];
__device__ __half g_h2  [(size_t)ROWS * OUT_CH];
__device__ __half g_qkv [(size_t)ROWS * 3 * OUT_CH];
__device__ __half g_at2 [(size_t)ROWS * OUT_CH];

// ---------------------------- helpers --------------------------------------
__device__ __forceinline__ uint32_t smem_u32(const void* p) {
    uint32_t a;
    asm("{ .reg .u64 t; cvta.to.shared.u64 t, %1; cvt.u32.u64 %0, t; }"
        : "=r"(a) : "l"(p));
    return a;
}
__device__ __forceinline__ void ldsm4(uint32_t* r, uint32_t addr) {
    asm volatile("ldmatrix.sync.aligned.m8n8.x4.shared.b16 {%0,%1,%2,%3}, [%4];"
                 : "=r"(r[0]), "=r"(r[1]), "=r"(r[2]), "=r"(r[3]) : "r"(addr));
}
__device__ __forceinline__ void mma16816(float* d, const uint32_t* a,
                                         uint32_t b0, uint32_t b1) {
    asm volatile("mma.sync.aligned.m16n8k16.row.col.f32.f16.f16.f32 "
                 "{%0,%1,%2,%3}, {%4,%5,%6,%7}, {%8,%9}, {%0,%1,%2,%3};"
                 : "+f"(d[0]), "+f"(d[1]), "+f"(d[2]), "+f"(d[3])
                 : "r"(a[0]), "r"(a[1]), "r"(a[2]), "r"(a[3]), "r"(b0), "r"(b1));
}
#define CP_ASYNC(dst, src) \
    asm volatile("cp.async.cg.shared.global [%0], [%1], 16;" :: "r"(dst), "l"(src))
#define CP_COMMIT() asm volatile("cp.async.commit_group;" ::: "memory")
#define CP_WAIT(n)  asm volatile("cp.async.wait_group %0;" :: "n"(n) : "memory")

__device__ __forceinline__ uint32_t pk2h(__half a, __half b) {
    return (uint32_t)__half_as_ushort(a) | ((uint32_t)__half_as_ushort(b) << 16);
}

// ---------------------------------------------------------------------------
// conv_all: single elementwise fp32->fp16 pass over all 6 tensors.
// float4 region offsets:
//   wd [0, 131072)  wt [131072, 196608)  wq [196608, 393216)
//   wo [393216, 458752)  t [458752, 1507328)  x [1507328, 18284544)
// ---------------------------------------------------------------------------
#define CONV_TOTAL4 18284544L

__global__ void conv_all(const float4* __restrict__ wd, const float4* __restrict__ wt,
                         const float4* __restrict__ wq, const float4* __restrict__ wo,
                         const float4* __restrict__ t,  const float4* __restrict__ x,
                         __half* __restrict__ od, __half* __restrict__ ot,
                         __half* __restrict__ oq, __half* __restrict__ oo,
                         __half* __restrict__ o_t, __half* __restrict__ o_x)
{
    long idx = (long)blockIdx.x * blockDim.x + threadIdx.x;
    if (idx >= CONV_TOTAL4) return;
    const float4* in; __half* out; long lidx;
    if (idx >= 1507328L)      { in = x;  out = o_x; lidx = idx - 1507328L; }
    else if (idx >= 458752L)  { in = t;  out = o_t; lidx = idx - 458752L; }
    else if (idx >= 393216L)  { in = wo; out = oo;  lidx = idx - 393216L; }
    else if (idx >= 196608L)  { in = wq; out = oq;  lidx = idx - 196608L; }
    else if (idx >= 131072L)  { in = wt; out = ot;  lidx = idx - 131072L; }
    else                      { in = wd; out = od;  lidx = idx; }
    float4 v = in[lidx];
    *(uint2*)(out + lidx * 4) =
        make_uint2(pk2h(__float2half_rn(v.x), __float2half_rn(v.y)),
                   pk2h(__float2half_rn(v.z), __float2half_rn(v.w)));
}

// ---------------------------------------------------------------------------
// GEMM: C[M,N] = A[M,K] @ W[N,K]^T + bias (+extra for MODE 1)
// Block 128x128, BK=64, 3-stage cp.async, 8 warps (2m x 4n), warp 64x32.
// MODE 0: fp32 out, row stride N.
// MODE 1: fp16 out, row stride 512, adds extra[m>>3, col] (temb).
// MODE 2: fp16 out, row stride N.
// ---------------------------------------------------------------------------
#define STAGES      3
#define STAGE_BYTES 32768    // A 16KB + B 16KB

template <int MODE>
__global__ __launch_bounds__(256, 2)
void gemm_mma(const __half* __restrict__ A, const __half* __restrict__ B,
              const float* __restrict__ bias, const float* __restrict__ extra,
              void* __restrict__ Cout, int N, int K)
{
    extern __shared__ char sm[];
    const uint32_t smemBase = smem_u32(sm);
    const int tid    = threadIdx.x;
    const int lane   = tid & 31;
    const int wid    = tid >> 5;
    const int warp_m = wid >> 2;
    const int warp_n = wid & 3;
    const int mB     = blockIdx.y * 128;
    const int nB     = blockIdx.x * 128;

    // cp.async: 2048 16B chunks/stage (A 1024 + B 1024), 8 per thread
    uint32_t dstOff[8];
    const __half* gsrc[8];
#pragma unroll
    for (int j = 0; j < 8; j++) {
        int chunk = tid + 256 * j;
        int isB   = chunk >> 10;
        int cc    = chunk & 1023;
        int row   = cc >> 3, c = cc & 7;
        dstOff[j] = isB * 16384 + row * 128 + ((c ^ (row & 7)) << 4);
        gsrc[j] = (isB ? B + (size_t)(nB + row) * K
                       : A + (size_t)(mB + row) * K) + c * 8;
    }

    // ldmatrix bases (stage 0, k-chunk 0)
    const int la = lane & 15, ha = lane >> 4;
    uint32_t baseA[4];
#pragma unroll
    for (int mi = 0; mi < 4; mi++) {
        int row = warp_m * 64 + mi * 16 + la;
        baseA[mi] = smemBase + row * 128 + ((ha ^ (row & 7)) << 4);
    }
    const int lb = (lane & 7) + ((lane >> 4) << 3);
    const int hb = (lane >> 3) & 1;
    uint32_t baseB[2];
#pragma unroll
    for (int n2 = 0; n2 < 2; n2++) {
        int row = warp_n * 32 + n2 * 16 + lb;
        baseB[n2] = smemBase + 16384 + row * 128 + ((hb ^ (row & 7)) << 4);
    }

    float acc[4][4][4];
#pragma unroll
    for (int mi = 0; mi < 4; mi++)
#pragma unroll
        for (int ni = 0; ni < 4; ni++)
#pragma unroll
            for (int e = 0; e < 4; e++) acc[mi][ni][e] = 0.f;

    const int nIter = K >> 6;

    // prologue: 2 stages
#pragma unroll
    for (int s = 0; s < STAGES - 1; s++) {
#pragma unroll
        for (int j = 0; j < 8; j++)
            CP_ASYNC(smemBase + s * STAGE_BYTES + dstOff[j], gsrc[j] + s * 64);
        CP_COMMIT();
    }

    int stage = 0;
    for (int it = 0; it < nIter; it++) {
        CP_WAIT(1);
        __syncthreads();

        if (it + STAGES - 1 < nIter) {
            const int pit = it + STAGES - 1;
            const int pstage = (stage + STAGES - 1 >= STAGES) ? stage - 1 : stage + 2;
            const int off = pit * 64;
#pragma unroll
            for (int j = 0; j < 8; j++)
                CP_ASYNC(smemBase + pstage * STAGE_BYTES + dstOff[j], gsrc[j] + off);
        }
        CP_COMMIT();

        const uint32_t stOff = (uint32_t)stage * STAGE_BYTES;
#pragma unroll
        for (int kk = 0; kk < 4; kk++) {
            uint32_t a[4][4], b[2][4];
#pragma unroll
            for (int mi = 0; mi < 4; mi++)
                ldsm4(a[mi], (baseA[mi] + stOff) ^ (kk << 5));
#pragma unroll
            for (int n2 = 0; n2 < 2; n2++)
                ldsm4(b[n2], (baseB[n2] + stOff) ^ (kk << 5));
#pragma unroll
            for (int mi = 0; mi < 4; mi++)
#pragma unroll
                for (int ni = 0; ni < 4; ni++)
                    mma16816(acc[mi][ni], a[mi],
                             b[ni >> 1][(ni & 1) * 2], b[ni >> 1][(ni & 1) * 2 + 1]);
        }
        stage = (stage + 1 == STAGES) ? 0 : stage + 1;
    }

    // ---------------- epilogue (bias hoisted out of mi loop) ----------------
    const int mWarp = mB + warp_m * 64;
    const int nWarp = nB + warp_n * 32;
    float bv[4][2];
#pragma unroll
    for (int ni = 0; ni < 4; ni++) {
        const int col = nWarp + ni * 8 + (lane & 3) * 2;
        bv[ni][0] = __ldg(bias + col);
        bv[ni][1] = __ldg(bias + col + 1);
    }
#pragma unroll
    for (int mi = 0; mi < 4; mi++) {
#pragma unroll
        for (int ni = 0; ni < 4; ni++) {
            const int row0 = mWarp + mi * 16 + (lane >> 2);
            const int col  = nWarp + ni * 8 + (lane & 3) * 2;
            float v0 = acc[mi][ni][0] + bv[ni][0], v1 = acc[mi][ni][1] + bv[ni][1];
            float v2 = acc[mi][ni][2] + bv[ni][0], v3 = acc[mi][ni][3] + bv[ni][1];
            if (MODE == 1) {
                const float* e0 = extra + (size_t)(row0 >> 3) * OUT_CH + col;
                const float* e1 = extra + (size_t)((row0 + 8) >> 3) * OUT_CH + col;
                v0 += __ldg(e0); v1 += __ldg(e0 + 1);
                v2 += __ldg(e1); v3 += __ldg(e1 + 1);
            }
            if (MODE == 0) {
                float* c0 = (float*)Cout + (size_t)row0 * N + col;
                float* c1 = (float*)Cout + (size_t)(row0 + 8) * N + col;
                *(float2*)c0 = make_float2(v0, v1);
                *(float2*)c1 = make_float2(v2, v3);
            } else {
                const int stride = (MODE == 1) ? OUT_CH : N;
                __half* o0 = (__half*)Cout + (size_t)row0 * stride + col;
                __half* o1 = (__half*)Cout + (size_t)(row0 + 8) * stride + col;
                *(uint32_t*)o0 = pk2h(__float2half_rn(v0), __float2half_rn(v1));
                *(uint32_t*)o1 = pk2h(__float2half_rn(v2), __float2half_rn(v3));
            }
        }
    }
}

// ---------------------------------------------------------------------------
// Per-row attention: raw half2 smem, shuffle softmax, one barrier.
// Block = 256 threads = 4 rows x 64 (qh,kh) threads.
// Row layout in smem: [q 512 | k 512 | v 512] halfs (verbatim qkv row).
// ---------------------------------------------------------------------------
__global__ __launch_bounds__(256)
void attn_kernel(const __half* __restrict__ qkv, __half* __restrict__ out2)
{
    __shared__ __align__(16) __half s[4][1536];   // 12 KB

    const int tid = threadIdx.x;
    const size_t rowBase = (size_t)blockIdx.x * 4;

    // cooperative raw copy: 4 rows x 1536 halfs = 12288 B = 768 uint4
    const uint4* src = (const uint4*)(qkv + rowBase * 1536);
    uint4* dst = (uint4*)&s[0][0];
    dst[tid]       = src[tid];
    dst[256 + tid] = src[256 + tid];
    dst[512 + tid] = src[512 + tid];
    __syncthreads();

    const int r  = tid >> 6;
    const int j  = tid & 63;
    const int qh = j >> 3;
    const int kh = j & 7;       // also the output chunk selector

    const __half* q = &s[r][0];
    const __half* k = &s[r][512];
    const __half* v = &s[r][1024];

    // ---- score: dot(q[qh], k[kh]) over 64 ch, 8 chunks of 8 halfs ----
    float sc = 0.f;
#pragma unroll
    for (int c = 0; c < 8; c++) {
        const int cc = (kh + c) & 7;                    // bank rotation
        uint4 qu = *(const uint4*)(q + qh * 64 + cc * 8);
        uint4 ku = *(const uint4*)(k + kh * 64 + cc * 8);
        const __half2* qp = (const __half2*)&qu;
        const __half2* kp = (const __half2*)&ku;
#pragma unroll
        for (int e = 0; e < 4; e++) {
            float2 a = __half22float2(qp[e]);
            float2 b = __half22float2(kp[e]);
            sc += a.x * b.x + a.y * b.y;
        }
    }
    sc *= 0.125f;   // (ch^-1/4)^2 = 1/8

    // ---- softmax over kh within each 8-lane group (shuffle butterflies) ----
    float mx = sc;
#pragma unroll
    for (int d = 1; d < 8; d <<= 1)
        mx = fmaxf(mx, __shfl_xor_sync(0xffffffffu, mx, d, 8));
    float e = __expf(sc - mx);
    float sum = e;
#pragma unroll
    for (int d = 1; d < 8; d <<= 1)
        sum += __shfl_xor_sync(0xffffffffu, sum, d, 8);
    const float wOwn = e / sum;     // this thread's w[qh][kh]

    // ---- output: channels qh*64 + kh*8 .. +8 ----
    const int lane = tid & 31;
    const int gBase = lane & 24;    // lane group base (qh within warp)
    float o[8];
#pragma unroll
    for (int i = 0; i < 8; i++) o[i] = 0.f;
#pragma unroll
    for (int kk = 0; kk < 8; kk++) {
        const int kh2 = (kk + kh) & 7;                  // bank rotation
        const float wv = __shfl_sync(0xffffffffu, wOwn, gBase + kh2);
        uint4 vu = *(const uint4*)(v + kh2 * 64 + kh * 8);
        const __half2* vp = (const __half2*)&vu;
#pragma unroll
        for (int ee = 0; ee < 4; ee++) {
            float2 b = __half22float2(vp[ee]);
            o[2 * ee]     += wv * b.x;
            o[2 * ee + 1] += wv * b.y;
        }
    }

    uint4 hv = make_uint4(
        pk2h(__float2half_rn(o[0]), __float2half_rn(o[1])),
        pk2h(__float2half_rn(o[2]), __float2half_rn(o[3])),
        pk2h(__float2half_rn(o[4]), __float2half_rn(o[5])),
        pk2h(__float2half_rn(o[6]), __float2half_rn(o[7])));
    __half* base = out2 + (rowBase + r) * 512 + qh * 64 + kh * 8;
    *(uint4*)base = hv;
}

// ---------------------------------------------------------------------------
extern "C" void kernel_launch(void* const* d_in, const int* in_sizes, int n_in,
                              void* d_out, int out_size)
{
    const float* x      = (const float*)d_in[0];
    const float* t      = (const float*)d_in[1];
    const float* W_down = (const float*)d_in[2];
    const float* b_down = (const float*)d_in[3];
    const float* W_t    = (const float*)d_in[4];
    const float* b_t    = (const float*)d_in[5];
    const float* W_qkv  = (const float*)d_in[6];
    const float* b_qkv  = (const float*)d_in[7];
    const float* W_out  = (const float*)d_in[8];
    const float* b_out  = (const float*)d_in[9];
    float* out = (float*)d_out;

    void* p;
    __half *t16, *x16, *wd2, *wt2, *wq2, *wo2, *h2, *qkv, *at2;
    float *temb;
    cudaGetSymbolAddress(&p, g_t16);  t16 = (__half*)p;
    cudaGetSymbolAddress(&p, g_x16);  x16 = (__half*)p;
    cudaGetSymbolAddress(&p, g_wd2);  wd2 = (__half*)p;
    cudaGetSymbolAddress(&p, g_wt2);  wt2 = (__half*)p;
    cudaGetSymbolAddress(&p, g_wq2);  wq2 = (__half*)p;
    cudaGetSymbolAddress(&p, g_wo2);  wo2 = (__half*)p;
    cudaGetSymbolAddress(&p, g_temb); temb = (float*)p;
    cudaGetSymbolAddress(&p, g_h2);   h2  = (__half*)p;
    cudaGetSymbolAddress(&p, g_qkv);  qkv = (__half*)p;
    cudaGetSymbolAddress(&p, g_at2);  at2 = (__half*)p;

    const int dynSmem = STAGES * STAGE_BYTES;   // 96 KB
    cudaFuncSetAttribute(gemm_mma<0>, cudaFuncAttributeMaxDynamicSharedMemorySize, dynSmem);
    cudaFuncSetAttribute(gemm_mma<1>, cudaFuncAttributeMaxDynamicSharedMemorySize, dynSmem);
    cudaFuncSetAttribute(gemm_mma<2>, cudaFuncAttributeMaxDynamicSharedMemorySize, dynSmem);

    // 0: all conversions in one wave
    conv_all<<<(int)((CONV_TOTAL4 + 255) / 256), 256>>>(
        (const float4*)W_down, (const float4*)W_t,
        (const float4*)W_qkv, (const float4*)W_out,
        (const float4*)t, (const float4*)x,
        wd2, wt2, wq2, wo2, t16, x16);

    // 1: temb = t @ W_t^T + b_t                       [8192, 512] fp32
    gemm_mma<0><<<dim3(4, 64), 256, dynSmem>>>(t16, wt2, b_t, nullptr, temb,
                                               OUT_CH, T_DIM);
    // 2: x2 = x @ W_down^T + b_down + temb -> fp16    [65536, 512]
    gemm_mma<1><<<dim3(4, 512), 256, dynSmem>>>(x16, wd2, b_down, temb, h2,
                                                OUT_CH, IN_CH);
    // 3: qkv = x2 @ W_qkv^T + b_qkv -> fp16           [65536, 1536]  (ncu slot)
    gemm_mma<2><<<dim3(12, 512), 256, dynSmem>>>(h2, wq2, b_qkv, nullptr, qkv,
                                                 3 * OUT_CH, OUT_CH);
    // 4: attention -> fp16                            [65536, 512]
    attn_kernel<<<ROWS / 4, 256>>>(qkv, at2);
    // 5: out = attn @ W_out^T + b_out                 [65536, 512] fp32
    gemm_mma<0><<<dim3(4, 512), 256, dynSmem>>>(at2, wo2, b_out, nullptr, out,
                                                OUT_CH, OUT_CH);
}